// round 5
// baseline (speedup 1.0000x reference)
#include <cuda_runtime.h>
#include <cuda_bf16.h>

// ---------------------------------------------------------------------------
// MHA, bf16 split-precision (hi+lo) tensor cores, cp.async pipelines.
// B=4, S=2048, D=512, H=8, HD=64.
//  0) one convert kernel: q,k,v,W* fp32 -> bf16 hi/lo planes
//  1) proj GEMMs 256x128 tiles (split-plane out, [B,H,S,HD] remap)
//  2) flash attn: 128-thr CTAs, 128 q-rows (32/warp), K/V frags loaded once
//  3) out GEMM (split-plane in, fp32 out + bias)
// ---------------------------------------------------------------------------

#define DI __device__ __forceinline__

DI unsigned sptr(const void* p) { return (unsigned)__cvta_generic_to_shared(p); }

DI void cpasync16(unsigned dst, const void* src) {
    asm volatile("cp.async.cg.shared.global [%0], [%1], 16;" :: "r"(dst), "l"(src));
}
DI void cpcommit() { asm volatile("cp.async.commit_group;"); }
template <int N> DI void cpwait() { asm volatile("cp.async.wait_group %0;" :: "n"(N)); }

DI void ldsm4(unsigned* r, unsigned a) {
    asm volatile("ldmatrix.sync.aligned.m8n8.x4.shared.b16 {%0,%1,%2,%3}, [%4];"
                 : "=r"(r[0]), "=r"(r[1]), "=r"(r[2]), "=r"(r[3]) : "r"(a));
}
DI void ldsm4t(unsigned* r, unsigned a) {
    asm volatile("ldmatrix.sync.aligned.m8n8.x4.trans.shared.b16 {%0,%1,%2,%3}, [%4];"
                 : "=r"(r[0]), "=r"(r[1]), "=r"(r[2]), "=r"(r[3]) : "r"(a));
}
DI void mma16816(float* c, const unsigned* a, const unsigned* b) {
    asm volatile(
        "mma.sync.aligned.m16n8k16.row.col.f32.bf16.bf16.f32 "
        "{%0,%1,%2,%3},{%4,%5,%6,%7},{%8,%9},{%0,%1,%2,%3};"
        : "+f"(c[0]), "+f"(c[1]), "+f"(c[2]), "+f"(c[3])
        : "r"(a[0]), "r"(a[1]), "r"(a[2]), "r"(a[3]), "r"(b[0]), "r"(b[1]));
}
DI unsigned pkbf(float e0, float e1) {   // pack (e0,e1) -> bf16x2, e0 low
    unsigned r;
    asm("cvt.rn.bf16x2.f32 %0, %1, %2;" : "=r"(r) : "f"(e1), "f"(e0));
    return r;
}
DI float bfr(float x) { return __bfloat162float(__float2bfloat16(x)); }
DI void split2(float a, float b, unsigned& hi, unsigned& lo) {
    float ah = bfr(a), bh = bfr(b);
    hi = pkbf(ah, bh);
    lo = pkbf(a - ah, b - bh);
}
DI float ex2(float x) {
    float r; asm("ex2.approx.f32 %0, %1;" : "=f"(r) : "f"(x)); return r;
}

// ---------------- scratch (allocation-free: device globals) ----------------
#define MD (8192 * 512)
#define WD (512 * 512)
__device__ __nv_bfloat16 g_qh[MD], g_ql[MD], g_kh[MD], g_kl[MD], g_vh[MD], g_vl[MD];
__device__ __nv_bfloat16 g_wqh[WD], g_wql[WD], g_wkh[WD], g_wkl[WD];
__device__ __nv_bfloat16 g_wvh[WD], g_wvl[WD], g_woh[WD], g_wol[WD];
__device__ __nv_bfloat16 g_Qh[MD], g_Ql[MD], g_Kh[MD], g_Kl[MD], g_Vh[MD], g_Vl[MD];
__device__ __nv_bfloat16 g_ch[MD], g_cl[MD];

// ---------------------------------------------------------------------------
// Single convert kernel for all 7 tensors (3 of MD, 4 of WD), float4 granular.
// ---------------------------------------------------------------------------
struct CvtArgs {
    const float* src[7];
    __nv_bfloat16* hi[7];
    __nv_bfloat16* lo[7];
};
#define MD4 (MD / 4)
#define WD4 (WD / 4)
__global__ void convert_all(CvtArgs a)
{
    const int total = 3 * MD4 + 4 * WD4;
    for (int i = blockIdx.x * blockDim.x + threadIdx.x; i < total;
         i += gridDim.x * blockDim.x) {
        int s, off;
        if (i < 3 * MD4) { s = i >> 20; off = i & (MD4 - 1); }
        else { int j = i - 3 * MD4; s = 3 + (j >> 16); off = j & (WD4 - 1); }
        float4 v = ((const float4*)a.src[s])[off];
        float hx = bfr(v.x), hy = bfr(v.y), hz = bfr(v.z), hw = bfr(v.w);
        uint2 h, l;
        h.x = pkbf(hx, hy);             h.y = pkbf(hz, hw);
        l.x = pkbf(v.x - hx, v.y - hy); l.y = pkbf(v.z - hz, v.w - hw);
        ((uint2*)a.hi[s])[off] = h;
        ((uint2*)a.lo[s])[off] = l;
    }
}

// ---------------------------------------------------------------------------
// GEMM: C[8192,512] = A @ W^T (+bias) (*scale). bf16 hi/lo planes in.
// Tile 256Mx128N, BK=32, 256 thr, warps 4(M)x2(N), warp tile 64x64.
// 2-stage cp.async. Grid (4,32)=128 CTAs = one wave at 1 CTA/SM.
// smem/stage: Ahi,Alo 256x40, Whi,Wlo 128x40 bf16 = 61440B.
// ---------------------------------------------------------------------------
#define GSTG 61440
#define GEMM_SMEM (2 * GSTG)
template <int OUT_SPLIT>
__global__ void __launch_bounds__(256, 1)
gemm_bf16(const __nv_bfloat16* __restrict__ Ahi, const __nv_bfloat16* __restrict__ Alo,
          const __nv_bfloat16* __restrict__ Whi, const __nv_bfloat16* __restrict__ Wlo,
          const float* __restrict__ bias, float scale,
          float* __restrict__ Cf,
          __nv_bfloat16* __restrict__ Chi, __nv_bfloat16* __restrict__ Clo)
{
    extern __shared__ __align__(16) unsigned char dsm[];
    const unsigned smb = sptr(dsm);
    const int tid = threadIdx.x, w = tid >> 5, lane = tid & 31;
    const int wm = w >> 1, wn = w & 1;
    const int m0 = blockIdx.y * 256, n0 = blockIdx.x * 128;

    float acc[4][8][4];
#pragma unroll
    for (int a = 0; a < 4; a++)
#pragma unroll
        for (int b = 0; b < 8; b++)
#pragma unroll
            for (int c = 0; c < 4; c++) acc[a][b][c] = 0.f;

#pragma unroll 1
    for (int step = -1; step < 16; step++) {
        int lt = step + 1;
        if (lt < 16) {
            unsigned sdst = smb + (lt & 1) * GSTG;
            int k0 = lt * 32;
            // A: 2048 chunks (2 planes x 256 rows x 4), W: 1024 chunks
#pragma unroll
            for (int c = 0; c < 12; c++) {
                int idx = tid + c * 256;
                if (idx < 2048) {
                    int p = idx >> 10, r = (idx >> 2) & 255, q = idx & 3;
                    const __nv_bfloat16* sp = p ? Alo : Ahi;
                    cpasync16(sdst + p * 20480 + r * 80 + q * 16,
                              sp + (m0 + r) * 512 + k0 + q * 8);
                } else {
                    int j = idx - 2048;
                    int p = j >> 9, r = (j >> 2) & 127, q = j & 3;
                    const __nv_bfloat16* sp = p ? Wlo : Whi;
                    cpasync16(sdst + 40960 + p * 10240 + r * 80 + q * 16,
                              sp + (n0 + r) * 512 + k0 + q * 8);
                }
            }
            cpcommit();
        }
        if (step < 0) continue;
        if (step < 15) cpwait<1>(); else cpwait<0>();
        __syncthreads();

        unsigned sa = smb + (step & 1) * GSTG;
#pragma unroll
        for (int ks = 0; ks < 2; ks++) {
            unsigned bh[4][4], bl[4][4];
#pragma unroll
            for (int np = 0; np < 4; np++) {
                unsigned boff = ((wn * 64 + np * 16 + (lane & 7) + ((lane >> 4) << 3)) * 40
                                 + ks * 16 + ((lane >> 3) & 1) * 8) * 2;
                ldsm4(bh[np], sa + 40960 + boff);
                ldsm4(bl[np], sa + 51200 + boff);
            }
#pragma unroll
            for (int mi = 0; mi < 4; mi++) {
                unsigned aoff = ((wm * 64 + mi * 16 + (lane & 15)) * 40
                                 + ks * 16 + ((lane >> 4) << 3)) * 2;
                unsigned ah[4], al[4];
                ldsm4(ah, sa + aoff);
                ldsm4(al, sa + 20480 + aoff);
#pragma unroll
                for (int np = 0; np < 4; np++) {
                    mma16816(acc[mi][np * 2],     ah, bh[np]);
                    mma16816(acc[mi][np * 2],     ah, bl[np]);
                    mma16816(acc[mi][np * 2],     al, bh[np]);
                    mma16816(acc[mi][np * 2 + 1], ah, bh[np] + 2);
                    mma16816(acc[mi][np * 2 + 1], ah, bl[np] + 2);
                    mma16816(acc[mi][np * 2 + 1], al, bh[np] + 2);
                }
            }
        }
        __syncthreads();
    }

    // epilogue
#pragma unroll
    for (int mi = 0; mi < 4; mi++) {
#pragma unroll
        for (int j = 0; j < 8; j++) {
            int n = n0 + wn * 64 + j * 8 + (lane & 3) * 2;
            float b0 = bias[n], b1 = bias[n + 1];
#pragma unroll
            for (int rr = 0; rr < 2; rr++) {
                int m = m0 + wm * 64 + mi * 16 + (lane >> 2) + rr * 8;
                float v0 = (acc[mi][j][rr * 2]     + b0) * scale;
                float v1 = (acc[mi][j][rr * 2 + 1] + b1) * scale;
                if (OUT_SPLIT) {
                    int bb = m >> 11, s = m & 2047, hh = n >> 6, hd = n & 63;
                    int o = (((bb << 3) + hh) * 2048 + s) * 64 + hd;
                    unsigned hv, lv; split2(v0, v1, hv, lv);
                    *(unsigned*)&Chi[o] = hv;
                    *(unsigned*)&Clo[o] = lv;
                } else {
                    *(float2*)&Cf[m * 512 + n] = make_float2(v0, v1);
                }
            }
        }
    }
}

// ---------------------------------------------------------------------------
// Flash attention. Block = (b,h,128 q rows), 128 threads, 4 warps.
// Warp w owns rows [32w, 32w+32) = 2 m16 row-blocks; K/V frags loaded ONCE
// per warp per tile and reused by both row-blocks (halves smem traffic).
// Q persists in smem (re-read per ks); log2-domain softmax.
// smem: Q 2x18432 = 36864; 2 stages x (K,V hi/lo 4x9216 = 36864) = 73728.
// Total 110592 -> 2 CTA/SM.
// ---------------------------------------------------------------------------
#define ASTG 36864
#define AQSZ 36864
#define ATTN_SMEM (AQSZ + 2 * ASTG)
__global__ void __launch_bounds__(128, 2)
attn_kernel(const __nv_bfloat16* __restrict__ Qh_, const __nv_bfloat16* __restrict__ Ql_,
            const __nv_bfloat16* __restrict__ Kh_, const __nv_bfloat16* __restrict__ Kl_,
            const __nv_bfloat16* __restrict__ Vh_, const __nv_bfloat16* __restrict__ Vl_,
            __nv_bfloat16* __restrict__ Ch, __nv_bfloat16* __restrict__ Cl)
{
    extern __shared__ __align__(16) unsigned char dsm[];
    const unsigned smb = sptr(dsm);
    const int tid = threadIdx.x, w = tid >> 5, lane = tid & 31;
    const int q0 = blockIdx.x * 128;
    const int h = blockIdx.y, b = blockIdx.z;
    const long base = (long)((b << 3) + h) * (2048 * 64);

    // ---- Q tile (128 rows, hi+lo) -> persistent smem ----
#pragma unroll
    for (int c = 0; c < 16; c++) {
        int idx = tid + c * 128;                 // 0..2047
        int p = idx >> 10, r = (idx >> 3) & 127, q = idx & 7;
        const __nv_bfloat16* src = (p ? Ql_ : Qh_) + base + (long)(q0 + r) * 64 + q * 8;
        cpasync16(smb + p * 18432 + r * 144 + q * 16, src);
    }
    cpcommit();

    float o[2][8][4];
#pragma unroll
    for (int rb = 0; rb < 2; rb++)
#pragma unroll
        for (int j = 0; j < 8; j++)
#pragma unroll
            for (int i = 0; i < 4; i++) o[rb][j][i] = 0.f;
    float rm[2][2] = {{-1e30f, -1e30f}, {-1e30f, -1e30f}};
    float rl[2][2] = {{0.f, 0.f}, {0.f, 0.f}};

#pragma unroll 1
    for (int t = -1; t < 32; t++) {
        int lt = t + 1;
        if (lt < 32) {  // prefetch K/V tile lt
            unsigned sdst = smb + AQSZ + (lt & 1) * ASTG;
            long coff = base + (long)lt * 64 * 64;
#pragma unroll
            for (int c = 0; c < 16; c++) {
                int idx = tid + c * 128;         // 0..2047
                int p = idx >> 9, r = (idx >> 3) & 63, q = idx & 7;
                const __nv_bfloat16* sp = (p == 0) ? Kh_ : (p == 1) ? Kl_
                                         : (p == 2) ? Vh_ : Vl_;
                cpasync16(sdst + p * 9216 + r * 144 + q * 16, sp + coff + r * 64 + q * 8);
            }
            cpcommit();
        }
        if (t < 0) { cpwait<1>(); __syncthreads(); continue; }  // Q ready after first commit pair
        if (t < 31) cpwait<1>(); else cpwait<0>();
        __syncthreads();

        unsigned stb = smb + AQSZ + (t & 1) * ASTG;

        // ---- S = Q @ K^T (both row blocks share K frags) ----
        float s[2][8][4];
#pragma unroll
        for (int rb = 0; rb < 2; rb++)
#pragma unroll
            for (int j = 0; j < 8; j++)
#pragma unroll
                for (int i = 0; i < 4; i++) s[rb][j][i] = 0.f;

#pragma unroll
        for (int ks = 0; ks < 4; ks++) {
            unsigned bh[4][4], bl[4][4];
#pragma unroll
            for (int np = 0; np < 4; np++) {
                unsigned boff = ((np * 16 + (lane & 7) + ((lane >> 4) << 3)) * 144
                                 + (ks * 16 + ((lane >> 3) & 1) * 8) * 2);
                ldsm4(bh[np], stb + boff);
                ldsm4(bl[np], stb + 9216 + boff);
            }
#pragma unroll
            for (int rb = 0; rb < 2; rb++) {
                unsigned qoff = (w * 32 + rb * 16 + (lane & 15)) * 144
                                + (ks * 16 + ((lane >> 4) << 3)) * 2;
                unsigned qh[4], ql[4];
                ldsm4(qh, smb + qoff);
                ldsm4(ql, smb + 18432 + qoff);
#pragma unroll
                for (int np = 0; np < 4; np++) {
                    mma16816(s[rb][np * 2],     qh, bh[np]);
                    mma16816(s[rb][np * 2],     qh, bl[np]);
                    mma16816(s[rb][np * 2],     ql, bh[np]);
                    mma16816(s[rb][np * 2 + 1], qh, bh[np] + 2);
                    mma16816(s[rb][np * 2 + 1], qh, bl[np] + 2);
                    mma16816(s[rb][np * 2 + 1], ql, bh[np] + 2);
                }
            }
        }

        // ---- online softmax (base-2) + P frags ----
        unsigned ph[2][4][4], pl[2][4][4];
#pragma unroll
        for (int rb = 0; rb < 2; rb++) {
#pragma unroll
            for (int rr = 0; rr < 2; rr++) {
                float mt = -1e30f;
#pragma unroll
                for (int j = 0; j < 8; j++)
                    mt = fmaxf(mt, fmaxf(s[rb][j][rr * 2], s[rb][j][rr * 2 + 1]));
                mt = fmaxf(mt, __shfl_xor_sync(0xffffffffu, mt, 1));
                mt = fmaxf(mt, __shfl_xor_sync(0xffffffffu, mt, 2));
                float mn = fmaxf(rm[rb][rr], mt);
                float corr = ex2(rm[rb][rr] - mn);
                rm[rb][rr] = mn;
                float ls = 0.f;
#pragma unroll
                for (int j = 0; j < 8; j++) {
                    float p0 = ex2(s[rb][j][rr * 2] - mn);
                    float p1 = ex2(s[rb][j][rr * 2 + 1] - mn);
                    s[rb][j][rr * 2] = p0; s[rb][j][rr * 2 + 1] = p1;
                    ls += p0 + p1;
                }
                ls += __shfl_xor_sync(0xffffffffu, ls, 1);
                ls += __shfl_xor_sync(0xffffffffu, ls, 2);
                rl[rb][rr] = rl[rb][rr] * corr + ls;
#pragma unroll
                for (int j = 0; j < 8; j++) {
                    o[rb][j][rr * 2] *= corr; o[rb][j][rr * 2 + 1] *= corr;
                }
            }
#pragma unroll
            for (int kc = 0; kc < 4; kc++) {
                split2(s[rb][2 * kc][0],     s[rb][2 * kc][1],     ph[rb][kc][0], pl[rb][kc][0]);
                split2(s[rb][2 * kc][2],     s[rb][2 * kc][3],     ph[rb][kc][1], pl[rb][kc][1]);
                split2(s[rb][2 * kc + 1][0], s[rb][2 * kc + 1][1], ph[rb][kc][2], pl[rb][kc][2]);
                split2(s[rb][2 * kc + 1][2], s[rb][2 * kc + 1][3], ph[rb][kc][3], pl[rb][kc][3]);
            }
        }

        // ---- O += P @ V (both row blocks share V frags) ----
#pragma unroll
        for (int ks = 0; ks < 4; ks++) {
            unsigned vrow = ks * 16 + (lane & 7) + ((lane >> 3) & 1) * 8;
#pragma unroll
            for (int dp = 0; dp < 4; dp++) {
                unsigned off = vrow * 144 + (dp * 16 + ((lane >> 4) << 3)) * 2;
                unsigned vh[4], vl[4];
                ldsm4t(vh, stb + 18432 + off);
                ldsm4t(vl, stb + 27648 + off);
#pragma unroll
                for (int rb = 0; rb < 2; rb++) {
                    mma16816(o[rb][dp * 2],     ph[rb][ks], vh);
                    mma16816(o[rb][dp * 2],     ph[rb][ks], vl);
                    mma16816(o[rb][dp * 2],     pl[rb][ks], vh);
                    mma16816(o[rb][dp * 2 + 1], ph[rb][ks], vh + 2);
                    mma16816(o[rb][dp * 2 + 1], ph[rb][ks], vl + 2);
                    mma16816(o[rb][dp * 2 + 1], pl[rb][ks], vh + 2);
                }
            }
        }
        __syncthreads();
    }

    // ---- normalize, split, write ctx planes [B,S,D] ----
#pragma unroll
    for (int rb = 0; rb < 2; rb++) {
#pragma unroll
        for (int rr = 0; rr < 2; rr++) {
            float inv = 1.f / rl[rb][rr];
            int rg = q0 + w * 32 + rb * 16 + (lane >> 2) + rr * 8;
#pragma unroll
            for (int j = 0; j < 8; j++) {
                int col = h * 64 + j * 8 + (lane & 3) * 2;
                int oix = (b * 2048 + rg) * 512 + col;
                unsigned hv, lv;
                split2(o[rb][j][rr * 2] * inv, o[rb][j][rr * 2 + 1] * inv, hv, lv);
                *(unsigned*)&Ch[oix] = hv;
                *(unsigned*)&Cl[oix] = lv;
            }
        }
    }
}

// ---------------------------------------------------------------------------
extern "C" void kernel_launch(void* const* d_in, const int* in_sizes, int n_in,
                              void* d_out, int out_size)
{
    const float* q  = (const float*)d_in[0];
    const float* k  = (const float*)d_in[1];
    const float* v  = (const float*)d_in[2];
    const float* Wq = (const float*)d_in[3];
    const float* bq = (const float*)d_in[4];
    const float* Wk = (const float*)d_in[5];
    const float* bk = (const float*)d_in[6];
    const float* Wv = (const float*)d_in[7];
    const float* bv = (const float*)d_in[8];
    const float* Wo = (const float*)d_in[9];
    const float* bo = (const float*)d_in[10];

    __nv_bfloat16 *qh, *ql, *kh, *kl, *vh, *vl;
    __nv_bfloat16 *wqh, *wql, *wkh, *wkl, *wvh, *wvl, *woh, *wol;
    __nv_bfloat16 *Qh, *Ql, *Kh, *Kl, *Vh, *Vl, *ch, *cl;
    cudaGetSymbolAddress((void**)&qh, g_qh);   cudaGetSymbolAddress((void**)&ql, g_ql);
    cudaGetSymbolAddress((void**)&kh, g_kh);   cudaGetSymbolAddress((void**)&kl, g_kl);
    cudaGetSymbolAddress((void**)&vh, g_vh);   cudaGetSymbolAddress((void**)&vl, g_vl);
    cudaGetSymbolAddress((void**)&wqh, g_wqh); cudaGetSymbolAddress((void**)&wql, g_wql);
    cudaGetSymbolAddress((void**)&wkh, g_wkh); cudaGetSymbolAddress((void**)&wkl, g_wkl);
    cudaGetSymbolAddress((void**)&wvh, g_wvh); cudaGetSymbolAddress((void**)&wvl, g_wvl);
    cudaGetSymbolAddress((void**)&woh, g_woh); cudaGetSymbolAddress((void**)&wol, g_wol);
    cudaGetSymbolAddress((void**)&Qh, g_Qh);   cudaGetSymbolAddress((void**)&Ql, g_Ql);
    cudaGetSymbolAddress((void**)&Kh, g_Kh);   cudaGetSymbolAddress((void**)&Kl, g_Kl);
    cudaGetSymbolAddress((void**)&Vh, g_Vh);   cudaGetSymbolAddress((void**)&Vl, g_Vl);
    cudaGetSymbolAddress((void**)&ch, g_ch);   cudaGetSymbolAddress((void**)&cl, g_cl);

    cudaFuncSetAttribute(gemm_bf16<0>, cudaFuncAttributeMaxDynamicSharedMemorySize, GEMM_SMEM);
    cudaFuncSetAttribute(gemm_bf16<1>, cudaFuncAttributeMaxDynamicSharedMemorySize, GEMM_SMEM);
    cudaFuncSetAttribute(attn_kernel, cudaFuncAttributeMaxDynamicSharedMemorySize, ATTN_SMEM);

    // 0) one convert kernel for everything
    CvtArgs ca;
    ca.src[0] = q;  ca.hi[0] = qh;  ca.lo[0] = ql;
    ca.src[1] = k;  ca.hi[1] = kh;  ca.lo[1] = kl;
    ca.src[2] = v;  ca.hi[2] = vh;  ca.lo[2] = vl;
    ca.src[3] = Wq; ca.hi[3] = wqh; ca.lo[3] = wql;
    ca.src[4] = Wk; ca.hi[4] = wkh; ca.lo[4] = wkl;
    ca.src[5] = Wv; ca.hi[5] = wvh; ca.lo[5] = wvl;
    ca.src[6] = Wo; ca.hi[6] = woh; ca.lo[6] = wol;
    convert_all<<<2048, 256>>>(ca);

    // 1) projections (Q pre-scaled by 0.125*log2e for base-2 softmax)
    dim3 gg(4, 32);
    const float qscale = 0.125f * 1.44269504088896f;
    gemm_bf16<1><<<gg, 256, GEMM_SMEM>>>(qh, ql, wqh, wql, bq, qscale, nullptr, Qh, Ql);
    gemm_bf16<1><<<gg, 256, GEMM_SMEM>>>(kh, kl, wkh, wkl, bk, 1.0f,   nullptr, Kh, Kl);
    gemm_bf16<1><<<gg, 256, GEMM_SMEM>>>(vh, vl, wvh, wvl, bv, 1.0f,   nullptr, Vh, Vl);

    // 2) attention: 512 CTAs x 128 threads, 128 q-rows each
    attn_kernel<<<dim3(16, 8, 4), 128, ATTN_SMEM>>>(Qh, Ql, Kh, Kl, Vh, Vl, ch, cl);

    // 3) output projection
    gemm_bf16<0><<<gg, 256, GEMM_SMEM>>>(ch, cl, woh, wol, bo, 1.0f, (float*)d_out, nullptr, nullptr);
}

// round 7
// speedup vs baseline: 1.0666x; 1.0666x over previous
#include <cuda_runtime.h>
#include <cuda_bf16.h>

// ---------------------------------------------------------------------------
// MHA, bf16 split-precision (hi+lo) mma.sync tensor cores (tcgen05 is not
// compilable under this harness's PTX target). B=4, S=2048, D=512, H=8, HD=64.
//  0) one convert kernel: q,k,v,W* fp32 -> bf16 hi/lo planes
//  1) merged QKV projection GEMM: 64x128 tiles, 128 thr, 3 CTA/SM,
//     grid.z selects q/k/v; split-plane out + [B,H,S,HD] remap; Q pre-scaled
//  2) flash attn (R4 config: 128 thr, 64 q-rows, 3 CTA/SM, log2 softmax)
//  3) out GEMM (same shape, fp32 out + bias)
// ---------------------------------------------------------------------------

#define DI __device__ __forceinline__

DI unsigned sptr(const void* p) { return (unsigned)__cvta_generic_to_shared(p); }

DI void cpasync16(unsigned dst, const void* src) {
    asm volatile("cp.async.cg.shared.global [%0], [%1], 16;" :: "r"(dst), "l"(src));
}
DI void cpcommit() { asm volatile("cp.async.commit_group;"); }
template <int N> DI void cpwait() { asm volatile("cp.async.wait_group %0;" :: "n"(N)); }

DI void ldsm4(unsigned* r, unsigned a) {
    asm volatile("ldmatrix.sync.aligned.m8n8.x4.shared.b16 {%0,%1,%2,%3}, [%4];"
                 : "=r"(r[0]), "=r"(r[1]), "=r"(r[2]), "=r"(r[3]) : "r"(a));
}
DI void ldsm4t(unsigned* r, unsigned a) {
    asm volatile("ldmatrix.sync.aligned.m8n8.x4.trans.shared.b16 {%0,%1,%2,%3}, [%4];"
                 : "=r"(r[0]), "=r"(r[1]), "=r"(r[2]), "=r"(r[3]) : "r"(a));
}
DI void mma16816(float* c, const unsigned* a, const unsigned* b) {
    asm volatile(
        "mma.sync.aligned.m16n8k16.row.col.f32.bf16.bf16.f32 "
        "{%0,%1,%2,%3},{%4,%5,%6,%7},{%8,%9},{%0,%1,%2,%3};"
        : "+f"(c[0]), "+f"(c[1]), "+f"(c[2]), "+f"(c[3])
        : "r"(a[0]), "r"(a[1]), "r"(a[2]), "r"(a[3]), "r"(b[0]), "r"(b[1]));
}
DI unsigned pkbf(float e0, float e1) {   // pack (e0,e1) -> bf16x2, e0 low
    unsigned r;
    asm("cvt.rn.bf16x2.f32 %0, %1, %2;" : "=r"(r) : "f"(e1), "f"(e0));
    return r;
}
DI float bfr(float x) { return __bfloat162float(__float2bfloat16(x)); }
DI void split2(float a, float b, unsigned& hi, unsigned& lo) {
    float ah = bfr(a), bh = bfr(b);
    hi = pkbf(ah, bh);
    lo = pkbf(a - ah, b - bh);
}
DI float ex2(float x) {
    float r; asm("ex2.approx.f32 %0, %1;" : "=f"(r) : "f"(x)); return r;
}

// ---------------- scratch (allocation-free: device globals) ----------------
#define MD (8192 * 512)
#define WD (512 * 512)
__device__ __nv_bfloat16 g_qh[MD], g_ql[MD], g_kh[MD], g_kl[MD], g_vh[MD], g_vl[MD];
__device__ __nv_bfloat16 g_wqh[WD], g_wql[WD], g_wkh[WD], g_wkl[WD];
__device__ __nv_bfloat16 g_wvh[WD], g_wvl[WD], g_woh[WD], g_wol[WD];
__device__ __nv_bfloat16 g_Qh[MD], g_Ql[MD], g_Kh[MD], g_Kl[MD], g_Vh[MD], g_Vl[MD];
__device__ __nv_bfloat16 g_ch[MD], g_cl[MD];

// ---------------------------------------------------------------------------
// Single convert kernel for all 7 tensors (3 of MD, 4 of WD), float4 granular.
// ---------------------------------------------------------------------------
struct CvtArgs {
    const float* src[7];
    __nv_bfloat16* hi[7];
    __nv_bfloat16* lo[7];
};
#define MD4 (MD / 4)
#define WD4 (WD / 4)
__global__ void convert_all(CvtArgs a)
{
    const int total = 3 * MD4 + 4 * WD4;
    for (int i = blockIdx.x * blockDim.x + threadIdx.x; i < total;
         i += gridDim.x * blockDim.x) {
        int s, off;
        if (i < 3 * MD4) { s = i >> 20; off = i & (MD4 - 1); }
        else { int j = i - 3 * MD4; s = 3 + (j >> 16); off = j & (WD4 - 1); }
        float4 v = ((const float4*)a.src[s])[off];
        float hx = bfr(v.x), hy = bfr(v.y), hz = bfr(v.z), hw = bfr(v.w);
        uint2 h, l;
        h.x = pkbf(hx, hy);             h.y = pkbf(hz, hw);
        l.x = pkbf(v.x - hx, v.y - hy); l.y = pkbf(v.z - hz, v.w - hw);
        ((uint2*)a.hi[s])[off] = h;
        ((uint2*)a.lo[s])[off] = l;
    }
}

// ---------------------------------------------------------------------------
// GEMM: C[8192,512] = A @ W^T (+bias)(*scale), bf16 hi/lo planes in.
// Tile 64Mx128N, BK=32, 128 threads, warps 2(M)x2(N), warp tile 32x64.
// 2-stage cp.async, 3 CTA/SM (smem 60KB/CTA). grid (4 n, 128 m, z).
// grid.z selects input/weight/bias/output set (merged QKV in one launch).
// smem/stage: Ahi,Alo 64x40 bf16 (5120B ea), Bhi,Blo 128x40 (10240B ea).
// ---------------------------------------------------------------------------
#define G3STG 30720
#define G3SMEM (2 * G3STG)
struct G3Args {
    const __nv_bfloat16* Ah[3];
    const __nv_bfloat16* Al[3];
    const __nv_bfloat16* Wh[3];
    const __nv_bfloat16* Wl[3];
    const float* bias[3];
    float scale[3];
    float* Cf[3];
    __nv_bfloat16* Ch[3];
    __nv_bfloat16* Cl[3];
};
template <int OUT_SPLIT>
__global__ void __launch_bounds__(128, 3)
gemm3(G3Args ga)
{
    extern __shared__ __align__(16) unsigned char dsm[];
    const unsigned smb = sptr(dsm);
    const int z = blockIdx.z;
    const __nv_bfloat16* __restrict__ Ahi = ga.Ah[z];
    const __nv_bfloat16* __restrict__ Alo = ga.Al[z];
    const __nv_bfloat16* __restrict__ Whi = ga.Wh[z];
    const __nv_bfloat16* __restrict__ Wlo = ga.Wl[z];
    const float* __restrict__ bias = ga.bias[z];
    const float scale = ga.scale[z];

    const int tid = threadIdx.x, w = tid >> 5, lane = tid & 31;
    const int wm = w >> 1, wn = w & 1;
    const int m0 = blockIdx.y * 64, n0 = blockIdx.x * 128;

    float acc[2][8][4];
#pragma unroll
    for (int a = 0; a < 2; a++)
#pragma unroll
        for (int b = 0; b < 8; b++)
#pragma unroll
            for (int c = 0; c < 4; c++) acc[a][b][c] = 0.f;

#pragma unroll 1
    for (int step = -1; step < 16; step++) {
        int lt = step + 1;
        if (lt < 16) {
            unsigned sdst = smb + (lt & 1) * G3STG;
            int k0 = lt * 32;
#pragma unroll
            for (int c = 0; c < 12; c++) {
                int idx = tid + c * 128;           // 0..1535
                if (idx < 512) {                   // A: 2 planes x 64 rows x 4
                    int p = idx >> 8, r = (idx >> 2) & 63, q = idx & 3;
                    const __nv_bfloat16* sp = p ? Alo : Ahi;
                    cpasync16(sdst + p * 5120 + r * 80 + q * 16,
                              sp + (m0 + r) * 512 + k0 + q * 8);
                } else {                           // W: 2 planes x 128 rows x 4
                    int j = idx - 512;
                    int p = j >> 9, r = (j >> 2) & 127, q = j & 3;
                    const __nv_bfloat16* sp = p ? Wlo : Whi;
                    cpasync16(sdst + 10240 + p * 10240 + r * 80 + q * 16,
                              sp + (n0 + r) * 512 + k0 + q * 8);
                }
            }
            cpcommit();
        }
        if (step < 0) continue;
        if (step < 15) cpwait<1>(); else cpwait<0>();
        __syncthreads();

        unsigned sa = smb + (step & 1) * G3STG;
#pragma unroll
        for (int ks = 0; ks < 2; ks++) {
            unsigned bh[4][4], bl[4][4];
#pragma unroll
            for (int np = 0; np < 4; np++) {
                unsigned boff = ((wn * 64 + np * 16 + (lane & 7) + ((lane >> 4) << 3)) * 40
                                 + ks * 16 + ((lane >> 3) & 1) * 8) * 2;
                ldsm4(bh[np], sa + 10240 + boff);
                ldsm4(bl[np], sa + 20480 + boff);
            }
#pragma unroll
            for (int mi = 0; mi < 2; mi++) {
                unsigned aoff = ((wm * 32 + mi * 16 + (lane & 15)) * 40
                                 + ks * 16 + ((lane >> 4) << 3)) * 2;
                unsigned ah[4], al[4];
                ldsm4(ah, sa + aoff);
                ldsm4(al, sa + 5120 + aoff);
#pragma unroll
                for (int np = 0; np < 4; np++) {
                    mma16816(acc[mi][np * 2],     ah, bh[np]);
                    mma16816(acc[mi][np * 2],     ah, bl[np]);
                    mma16816(acc[mi][np * 2],     al, bh[np]);
                    mma16816(acc[mi][np * 2 + 1], ah, bh[np] + 2);
                    mma16816(acc[mi][np * 2 + 1], ah, bl[np] + 2);
                    mma16816(acc[mi][np * 2 + 1], al, bh[np] + 2);
                }
            }
        }
        __syncthreads();
    }

    // epilogue
#pragma unroll
    for (int mi = 0; mi < 2; mi++) {
#pragma unroll
        for (int j = 0; j < 8; j++) {
            int n = n0 + wn * 64 + j * 8 + (lane & 3) * 2;
            float b0 = bias[n], b1 = bias[n + 1];
#pragma unroll
            for (int rr = 0; rr < 2; rr++) {
                int m = m0 + wm * 32 + mi * 16 + (lane >> 2) + rr * 8;
                float v0 = (acc[mi][j][rr * 2]     + b0) * scale;
                float v1 = (acc[mi][j][rr * 2 + 1] + b1) * scale;
                if (OUT_SPLIT) {
                    int bb = m >> 11, s = m & 2047, hh = n >> 6, hd = n & 63;
                    int o = (((bb << 3) + hh) * 2048 + s) * 64 + hd;
                    unsigned hv, lv; split2(v0, v1, hv, lv);
                    *(unsigned*)&ga.Ch[z][o] = hv;
                    *(unsigned*)&ga.Cl[z][o] = lv;
                } else {
                    *(float2*)&ga.Cf[z][m * 512 + n] = make_float2(v0, v1);
                }
            }
        }
    }
}

// ---------------------------------------------------------------------------
// Flash attention (R4 config). Block = (b,h,64 q rows), 128 threads, 3 CTA/SM.
// Softmax in log2 domain (Q pre-scaled by 0.125*log2e; ex2.approx).
// smem/stage: Khi,Klo,Vhi,Vlo each 64x72 bf16 = 9216B -> 36864B; 2 stages.
// ---------------------------------------------------------------------------
#define ASTG 36864
#define ATTN_SMEM (2 * ASTG)
__global__ void __launch_bounds__(128, 3)
attn_kernel(const __nv_bfloat16* __restrict__ Qh_, const __nv_bfloat16* __restrict__ Ql_,
            const __nv_bfloat16* __restrict__ Kh_, const __nv_bfloat16* __restrict__ Kl_,
            const __nv_bfloat16* __restrict__ Vh_, const __nv_bfloat16* __restrict__ Vl_,
            __nv_bfloat16* __restrict__ Ch, __nv_bfloat16* __restrict__ Cl)
{
    extern __shared__ __align__(16) unsigned char dsm[];
    const unsigned smb = sptr(dsm);
    const int tid = threadIdx.x, w = tid >> 5, lane = tid & 31;
    const int q0 = blockIdx.x * 64;
    const int h = blockIdx.y, b = blockIdx.z;
    const long base = (long)((b << 3) + h) * (2048 * 64);

    // ---- Q tile (64 rows) -> smem (aliased in stage0) -> registers ----
#pragma unroll
    for (int c = 0; c < 8; c++) {
        int idx = tid + c * 128;                 // 0..1023
        int p = idx >> 9, r = (idx >> 3) & 63, q = idx & 7;
        const __nv_bfloat16* src = (p ? Ql_ : Qh_) + base + (long)(q0 + r) * 64 + q * 8;
        cpasync16(smb + p * 9216 + r * 144 + q * 16, src);
    }
    cpcommit(); cpwait<0>();
    __syncthreads();

    unsigned qh[4][4], ql[4][4];
#pragma unroll
    for (int ks = 0; ks < 4; ks++) {
        unsigned off = (w * 16 + (lane & 15)) * 144 + (ks * 16 + ((lane >> 4) << 3)) * 2;
        ldsm4(qh[ks], smb + off);
        ldsm4(ql[ks], smb + 9216 + off);
    }
    __syncthreads();

    float o[8][4];
#pragma unroll
    for (int j = 0; j < 8; j++)
#pragma unroll
        for (int i = 0; i < 4; i++) o[j][i] = 0.f;
    float rm[2] = {-1e30f, -1e30f}, rl[2] = {0.f, 0.f};

#pragma unroll 1
    for (int t = -1; t < 32; t++) {
        int lt = t + 1;
        if (lt < 32) {  // prefetch tile lt
            unsigned sdst = smb + (lt & 1) * ASTG;
            long coff = base + (long)lt * 64 * 64;
#pragma unroll
            for (int c = 0; c < 16; c++) {
                int idx = tid + c * 128;         // 0..2047
                int p = idx >> 9, r = (idx >> 3) & 63, q = idx & 7;
                const __nv_bfloat16* sp = (p == 0) ? Kh_ : (p == 1) ? Kl_
                                         : (p == 2) ? Vh_ : Vl_;
                cpasync16(sdst + p * 9216 + r * 144 + q * 16, sp + coff + r * 64 + q * 8);
            }
            cpcommit();
        }
        if (t < 0) continue;
        if (t < 31) cpwait<1>(); else cpwait<0>();
        __syncthreads();

        unsigned stb = smb + (t & 1) * ASTG;

        // ---- S = Q @ K^T (log2-domain scores) ----
        float s[8][4];
#pragma unroll
        for (int j = 0; j < 8; j++)
#pragma unroll
            for (int i = 0; i < 4; i++) s[j][i] = 0.f;

#pragma unroll
        for (int ks = 0; ks < 4; ks++) {
#pragma unroll
            for (int np = 0; np < 4; np++) {
                unsigned boff = ((np * 16 + (lane & 7) + ((lane >> 4) << 3)) * 144
                                 + (ks * 16 + ((lane >> 3) & 1) * 8) * 2);
                unsigned bh[4], bl[4];
                ldsm4(bh, stb + boff);
                ldsm4(bl, stb + 9216 + boff);
                mma16816(s[np * 2],     qh[ks], bh);
                mma16816(s[np * 2],     qh[ks], bl);
                mma16816(s[np * 2],     ql[ks], bh);
                mma16816(s[np * 2 + 1], qh[ks], bh + 2);
                mma16816(s[np * 2 + 1], qh[ks], bl + 2);
                mma16816(s[np * 2 + 1], ql[ks], bh + 2);
            }
        }

        // ---- online softmax (base-2) ----
#pragma unroll
        for (int rr = 0; rr < 2; rr++) {
            float mt = -1e30f;
#pragma unroll
            for (int j = 0; j < 8; j++)
                mt = fmaxf(mt, fmaxf(s[j][rr * 2], s[j][rr * 2 + 1]));
            mt = fmaxf(mt, __shfl_xor_sync(0xffffffffu, mt, 1));
            mt = fmaxf(mt, __shfl_xor_sync(0xffffffffu, mt, 2));
            float mn = fmaxf(rm[rr], mt);
            float corr = ex2(rm[rr] - mn);
            rm[rr] = mn;
            float ls = 0.f;
#pragma unroll
            for (int j = 0; j < 8; j++) {
                float p0 = ex2(s[j][rr * 2] - mn);
                float p1 = ex2(s[j][rr * 2 + 1] - mn);
                s[j][rr * 2] = p0; s[j][rr * 2 + 1] = p1;
                ls += p0 + p1;
            }
            ls += __shfl_xor_sync(0xffffffffu, ls, 1);
            ls += __shfl_xor_sync(0xffffffffu, ls, 2);
            rl[rr] = rl[rr] * corr + ls;
#pragma unroll
            for (int j = 0; j < 8; j++) {
                o[j][rr * 2] *= corr; o[j][rr * 2 + 1] *= corr;
            }
        }

        // ---- P fragments (S C-frag layout == PV A-frag layout) ----
        unsigned ph[4][4], pl[4][4];
#pragma unroll
        for (int kc = 0; kc < 4; kc++) {
            split2(s[2 * kc][0],     s[2 * kc][1],     ph[kc][0], pl[kc][0]);
            split2(s[2 * kc][2],     s[2 * kc][3],     ph[kc][1], pl[kc][1]);
            split2(s[2 * kc + 1][0], s[2 * kc + 1][1], ph[kc][2], pl[kc][2]);
            split2(s[2 * kc + 1][2], s[2 * kc + 1][3], ph[kc][3], pl[kc][3]);
        }

        // ---- O += P @ V ----
#pragma unroll
        for (int ks = 0; ks < 4; ks++) {
            unsigned vrow = ks * 16 + (lane & 7) + ((lane >> 3) & 1) * 8;
#pragma unroll
            for (int dp = 0; dp < 4; dp++) {
                unsigned off = vrow * 144 + (dp * 16 + ((lane >> 4) << 3)) * 2;
                unsigned bh[4], bl[4];
                ldsm4t(bh, stb + 18432 + off);
                ldsm4t(bl, stb + 27648 + off);
                mma16816(o[dp * 2],     ph[ks], bh);
                mma16816(o[dp * 2],     ph[ks], bl);
                mma16816(o[dp * 2],     pl[ks], bh);
                mma16816(o[dp * 2 + 1], ph[ks], bh + 2);
                mma16816(o[dp * 2 + 1], ph[ks], bl + 2);
                mma16816(o[dp * 2 + 1], pl[ks], bh + 2);
            }
        }
        __syncthreads();
    }

    // ---- normalize, split, write ctx planes [B,S,D] ----
#pragma unroll
    for (int rr = 0; rr < 2; rr++) {
        float inv = 1.f / rl[rr];
        int rg = q0 + w * 16 + (lane >> 2) + rr * 8;
#pragma unroll
        for (int j = 0; j < 8; j++) {
            int col = h * 64 + j * 8 + (lane & 3) * 2;
            int oix = (b * 2048 + rg) * 512 + col;
            unsigned hv, lv;
            split2(o[j][rr * 2] * inv, o[j][rr * 2 + 1] * inv, hv, lv);
            *(unsigned*)&Ch[oix] = hv;
            *(unsigned*)&Cl[oix] = lv;
        }
    }
}

// ---------------------------------------------------------------------------
extern "C" void kernel_launch(void* const* d_in, const int* in_sizes, int n_in,
                              void* d_out, int out_size)
{
    const float* q  = (const float*)d_in[0];
    const float* k  = (const float*)d_in[1];
    const float* v  = (const float*)d_in[2];
    const float* Wq = (const float*)d_in[3];
    const float* bq = (const float*)d_in[4];
    const float* Wk = (const float*)d_in[5];
    const float* bk = (const float*)d_in[6];
    const float* Wv = (const float*)d_in[7];
    const float* bv = (const float*)d_in[8];
    const float* Wo = (const float*)d_in[9];
    const float* bo = (const float*)d_in[10];

    __nv_bfloat16 *qh, *ql, *kh, *kl, *vh, *vl;
    __nv_bfloat16 *wqh, *wql, *wkh, *wkl, *wvh, *wvl, *woh, *wol;
    __nv_bfloat16 *Qh, *Ql, *Kh, *Kl, *Vh, *Vl, *ch, *cl;
    cudaGetSymbolAddress((void**)&qh, g_qh);   cudaGetSymbolAddress((void**)&ql, g_ql);
    cudaGetSymbolAddress((void**)&kh, g_kh);   cudaGetSymbolAddress((void**)&kl, g_kl);
    cudaGetSymbolAddress((void**)&vh, g_vh);   cudaGetSymbolAddress((void**)&vl, g_vl);
    cudaGetSymbolAddress((void**)&wqh, g_wqh); cudaGetSymbolAddress((void**)&wql, g_wql);
    cudaGetSymbolAddress((void**)&wkh, g_wkh); cudaGetSymbolAddress((void**)&wkl, g_wkl);
    cudaGetSymbolAddress((void**)&wvh, g_wvh); cudaGetSymbolAddress((void**)&wvl, g_wvl);
    cudaGetSymbolAddress((void**)&woh, g_woh); cudaGetSymbolAddress((void**)&wol, g_wol);
    cudaGetSymbolAddress((void**)&Qh, g_Qh);   cudaGetSymbolAddress((void**)&Ql, g_Ql);
    cudaGetSymbolAddress((void**)&Kh, g_Kh);   cudaGetSymbolAddress((void**)&Kl, g_Kl);
    cudaGetSymbolAddress((void**)&Vh, g_Vh);   cudaGetSymbolAddress((void**)&Vl, g_Vl);
    cudaGetSymbolAddress((void**)&ch, g_ch);   cudaGetSymbolAddress((void**)&cl, g_cl);

    cudaFuncSetAttribute(gemm3<0>, cudaFuncAttributeMaxDynamicSharedMemorySize, G3SMEM);
    cudaFuncSetAttribute(gemm3<1>, cudaFuncAttributeMaxDynamicSharedMemorySize, G3SMEM);
    cudaFuncSetAttribute(attn_kernel, cudaFuncAttributeMaxDynamicSharedMemorySize, ATTN_SMEM);

    // 0) one convert kernel for everything
    CvtArgs ca;
    ca.src[0] = q;  ca.hi[0] = qh;  ca.lo[0] = ql;
    ca.src[1] = k;  ca.hi[1] = kh;  ca.lo[1] = kl;
    ca.src[2] = v;  ca.hi[2] = vh;  ca.lo[2] = vl;
    ca.src[3] = Wq; ca.hi[3] = wqh; ca.lo[3] = wql;
    ca.src[4] = Wk; ca.hi[4] = wkh; ca.lo[4] = wkl;
    ca.src[5] = Wv; ca.hi[5] = wvh; ca.lo[5] = wvl;
    ca.src[6] = Wo; ca.hi[6] = woh; ca.lo[6] = wol;
    convert_all<<<2048, 256>>>(ca);

    // 1) merged QKV projections (Q pre-scaled by 0.125*log2e for base-2 softmax)
    const float qscale = 0.125f * 1.44269504088896f;
    G3Args gq = {};
    gq.Ah[0] = qh; gq.Al[0] = ql; gq.Wh[0] = wqh; gq.Wl[0] = wql;
    gq.bias[0] = bq; gq.scale[0] = qscale; gq.Ch[0] = Qh; gq.Cl[0] = Ql;
    gq.Ah[1] = kh; gq.Al[1] = kl; gq.Wh[1] = wkh; gq.Wl[1] = wkl;
    gq.bias[1] = bk; gq.scale[1] = 1.0f;   gq.Ch[1] = Kh; gq.Cl[1] = Kl;
    gq.Ah[2] = vh; gq.Al[2] = vl; gq.Wh[2] = wvh; gq.Wl[2] = wvl;
    gq.bias[2] = bv; gq.scale[2] = 1.0f;   gq.Ch[2] = Vh; gq.Cl[2] = Vl;
    gemm3<1><<<dim3(4, 128, 3), 128, G3SMEM>>>(gq);

    // 2) attention: 1024 CTAs x 128 threads, 64 q-rows each
    attn_kernel<<<dim3(32, 8, 4), 128, ATTN_SMEM>>>(Qh, Ql, Kh, Kl, Vh, Vl, ch, cl);

    // 3) output projection (fp32 out + bias)
    G3Args go = {};
    go.Ah[0] = ch; go.Al[0] = cl; go.Wh[0] = woh; go.Wl[0] = wol;
    go.bias[0] = bo; go.scale[0] = 1.0f; go.Cf[0] = (float*)d_out;
    gemm3<0><<<dim3(4, 128, 1), 128, G3SMEM>>>(go);
}

// round 8
// speedup vs baseline: 1.0779x; 1.0107x over previous
#include <cuda_runtime.h>
#include <cuda_bf16.h>

// ---------------------------------------------------------------------------
// MHA, bf16 split-precision (hi+lo) mma.sync tensor cores (tcgen05 not
// available under this harness's compute_103 PTX target).
// B=4, S=2048, D=512, H=8, HD=64.
//  0) one convert kernel: q,k,v,W* fp32 -> bf16 hi/lo planes
//  1) merged QKV projection GEMM: 64x128 tiles, 128 thr, 3 CTA/SM
//  2) flash attn (128 thr, 64 q-rows, 3 CTA/SM, log2 softmax)
//  3) out GEMM (fp32 out + bias)
// R8: MMA emission reordered term-outermost to break accumulator RAW chains.
// ---------------------------------------------------------------------------

#define DI __device__ __forceinline__

DI unsigned sptr(const void* p) { return (unsigned)__cvta_generic_to_shared(p); }

DI void cpasync16(unsigned dst, const void* src) {
    asm volatile("cp.async.cg.shared.global [%0], [%1], 16;" :: "r"(dst), "l"(src));
}
DI void cpcommit() { asm volatile("cp.async.commit_group;"); }
template <int N> DI void cpwait() { asm volatile("cp.async.wait_group %0;" :: "n"(N)); }

DI void ldsm4(unsigned* r, unsigned a) {
    asm volatile("ldmatrix.sync.aligned.m8n8.x4.shared.b16 {%0,%1,%2,%3}, [%4];"
                 : "=r"(r[0]), "=r"(r[1]), "=r"(r[2]), "=r"(r[3]) : "r"(a));
}
DI void ldsm4t(unsigned* r, unsigned a) {
    asm volatile("ldmatrix.sync.aligned.m8n8.x4.trans.shared.b16 {%0,%1,%2,%3}, [%4];"
                 : "=r"(r[0]), "=r"(r[1]), "=r"(r[2]), "=r"(r[3]) : "r"(a));
}
DI void mma16816(float* c, const unsigned* a, const unsigned* b) {
    asm volatile(
        "mma.sync.aligned.m16n8k16.row.col.f32.bf16.bf16.f32 "
        "{%0,%1,%2,%3},{%4,%5,%6,%7},{%8,%9},{%0,%1,%2,%3};"
        : "+f"(c[0]), "+f"(c[1]), "+f"(c[2]), "+f"(c[3])
        : "r"(a[0]), "r"(a[1]), "r"(a[2]), "r"(a[3]), "r"(b[0]), "r"(b[1]));
}
DI unsigned pkbf(float e0, float e1) {   // pack (e0,e1) -> bf16x2, e0 low
    unsigned r;
    asm("cvt.rn.bf16x2.f32 %0, %1, %2;" : "=r"(r) : "f"(e1), "f"(e0));
    return r;
}
DI float bfr(float x) { return __bfloat162float(__float2bfloat16(x)); }
DI void split2(float a, float b, unsigned& hi, unsigned& lo) {
    float ah = bfr(a), bh = bfr(b);
    hi = pkbf(ah, bh);
    lo = pkbf(a - ah, b - bh);
}
DI float ex2(float x) {
    float r; asm("ex2.approx.f32 %0, %1;" : "=f"(r) : "f"(x)); return r;
}

// ---------------- scratch (allocation-free: device globals) ----------------
#define MD (8192 * 512)
#define WD (512 * 512)
__device__ __nv_bfloat16 g_qh[MD], g_ql[MD], g_kh[MD], g_kl[MD], g_vh[MD], g_vl[MD];
__device__ __nv_bfloat16 g_wqh[WD], g_wql[WD], g_wkh[WD], g_wkl[WD];
__device__ __nv_bfloat16 g_wvh[WD], g_wvl[WD], g_woh[WD], g_wol[WD];
__device__ __nv_bfloat16 g_Qh[MD], g_Ql[MD], g_Kh[MD], g_Kl[MD], g_Vh[MD], g_Vl[MD];
__device__ __nv_bfloat16 g_ch[MD], g_cl[MD];

// ---------------------------------------------------------------------------
// Single convert kernel for all 7 tensors (3 of MD, 4 of WD), float4 granular.
// ---------------------------------------------------------------------------
struct CvtArgs {
    const float* src[7];
    __nv_bfloat16* hi[7];
    __nv_bfloat16* lo[7];
};
#define MD4 (MD / 4)
#define WD4 (WD / 4)
__global__ void convert_all(CvtArgs a)
{
    const int total = 3 * MD4 + 4 * WD4;
    for (int i = blockIdx.x * blockDim.x + threadIdx.x; i < total;
         i += gridDim.x * blockDim.x) {
        int s, off;
        if (i < 3 * MD4) { s = i >> 20; off = i & (MD4 - 1); }
        else { int j = i - 3 * MD4; s = 3 + (j >> 16); off = j & (WD4 - 1); }
        float4 v = ((const float4*)a.src[s])[off];
        float hx = bfr(v.x), hy = bfr(v.y), hz = bfr(v.z), hw = bfr(v.w);
        uint2 h, l;
        h.x = pkbf(hx, hy);             h.y = pkbf(hz, hw);
        l.x = pkbf(v.x - hx, v.y - hy); l.y = pkbf(v.z - hz, v.w - hw);
        ((uint2*)a.hi[s])[off] = h;
        ((uint2*)a.lo[s])[off] = l;
    }
}

// ---------------------------------------------------------------------------
// GEMM: C[8192,512] = A @ W^T (+bias)(*scale), bf16 hi/lo planes in.
// Tile 64Mx128N, BK=32, 128 threads, warps 2(M)x2(N), warp tile 32x64.
// 2-stage cp.async, 3 CTA/SM. grid (4 n, 128 m, z = q/k/v set).
// MMA emission: term-outermost (same-accumulator distance 16).
// ---------------------------------------------------------------------------
#define G3STG 30720
#define G3SMEM (2 * G3STG)
struct G3Args {
    const __nv_bfloat16* Ah[3];
    const __nv_bfloat16* Al[3];
    const __nv_bfloat16* Wh[3];
    const __nv_bfloat16* Wl[3];
    const float* bias[3];
    float scale[3];
    float* Cf[3];
    __nv_bfloat16* Ch[3];
    __nv_bfloat16* Cl[3];
};
template <int OUT_SPLIT>
__global__ void __launch_bounds__(128, 3)
gemm3(G3Args ga)
{
    extern __shared__ __align__(16) unsigned char dsm[];
    const unsigned smb = sptr(dsm);
    const int z = blockIdx.z;
    const __nv_bfloat16* __restrict__ Ahi = ga.Ah[z];
    const __nv_bfloat16* __restrict__ Alo = ga.Al[z];
    const __nv_bfloat16* __restrict__ Whi = ga.Wh[z];
    const __nv_bfloat16* __restrict__ Wlo = ga.Wl[z];
    const float* __restrict__ bias = ga.bias[z];
    const float scale = ga.scale[z];

    const int tid = threadIdx.x, w = tid >> 5, lane = tid & 31;
    const int wm = w >> 1, wn = w & 1;
    const int m0 = blockIdx.y * 64, n0 = blockIdx.x * 128;

    float acc[2][8][4];
#pragma unroll
    for (int a = 0; a < 2; a++)
#pragma unroll
        for (int b = 0; b < 8; b++)
#pragma unroll
            for (int c = 0; c < 4; c++) acc[a][b][c] = 0.f;

#pragma unroll 1
    for (int step = -1; step < 16; step++) {
        int lt = step + 1;
        if (lt < 16) {
            unsigned sdst = smb + (lt & 1) * G3STG;
            int k0 = lt * 32;
#pragma unroll
            for (int c = 0; c < 12; c++) {
                int idx = tid + c * 128;           // 0..1535
                if (idx < 512) {                   // A: 2 planes x 64 rows x 4
                    int p = idx >> 8, r = (idx >> 2) & 63, q = idx & 3;
                    const __nv_bfloat16* sp = p ? Alo : Ahi;
                    cpasync16(sdst + p * 5120 + r * 80 + q * 16,
                              sp + (m0 + r) * 512 + k0 + q * 8);
                } else {                           // W: 2 planes x 128 rows x 4
                    int j = idx - 512;
                    int p = j >> 9, r = (j >> 2) & 127, q = j & 3;
                    const __nv_bfloat16* sp = p ? Wlo : Whi;
                    cpasync16(sdst + 10240 + p * 10240 + r * 80 + q * 16,
                              sp + (n0 + r) * 512 + k0 + q * 8);
                }
            }
            cpcommit();
        }
        if (step < 0) continue;
        if (step < 15) cpwait<1>(); else cpwait<0>();
        __syncthreads();

        unsigned sa = smb + (step & 1) * G3STG;
#pragma unroll
        for (int ks = 0; ks < 2; ks++) {
            // preload ALL fragments for this ks
            unsigned bh[4][4], bl[4][4];
#pragma unroll
            for (int np = 0; np < 4; np++) {
                unsigned boff = ((wn * 64 + np * 16 + (lane & 7) + ((lane >> 4) << 3)) * 40
                                 + ks * 16 + ((lane >> 3) & 1) * 8) * 2;
                ldsm4(bh[np], sa + 10240 + boff);
                ldsm4(bl[np], sa + 20480 + boff);
            }
            unsigned ah[2][4], al[2][4];
#pragma unroll
            for (int mi = 0; mi < 2; mi++) {
                unsigned aoff = ((wm * 32 + mi * 16 + (lane & 15)) * 40
                                 + ks * 16 + ((lane >> 4) << 3)) * 2;
                ldsm4(ah[mi], sa + aoff);
                ldsm4(al[mi], sa + 5120 + aoff);
            }
            // term-outer emission: same-acc RAW distance = 16 MMAs
#pragma unroll
            for (int term = 0; term < 3; term++) {
#pragma unroll
                for (int mi = 0; mi < 2; mi++) {
                    const unsigned* a = (term == 2) ? al[mi] : ah[mi];
#pragma unroll
                    for (int np = 0; np < 4; np++) {
                        const unsigned* b = (term == 1) ? bl[np] : bh[np];
                        mma16816(acc[mi][np * 2],     a, b);
                        mma16816(acc[mi][np * 2 + 1], a, b + 2);
                    }
                }
            }
        }
        __syncthreads();
    }

    // epilogue
#pragma unroll
    for (int mi = 0; mi < 2; mi++) {
#pragma unroll
        for (int j = 0; j < 8; j++) {
            int n = n0 + wn * 64 + j * 8 + (lane & 3) * 2;
            float b0 = bias[n], b1 = bias[n + 1];
#pragma unroll
            for (int rr = 0; rr < 2; rr++) {
                int m = m0 + wm * 32 + mi * 16 + (lane >> 2) + rr * 8;
                float v0 = (acc[mi][j][rr * 2]     + b0) * scale;
                float v1 = (acc[mi][j][rr * 2 + 1] + b1) * scale;
                if (OUT_SPLIT) {
                    int bb = m >> 11, s = m & 2047, hh = n >> 6, hd = n & 63;
                    int o = (((bb << 3) + hh) * 2048 + s) * 64 + hd;
                    unsigned hv, lv; split2(v0, v1, hv, lv);
                    *(unsigned*)&ga.Ch[z][o] = hv;
                    *(unsigned*)&ga.Cl[z][o] = lv;
                } else {
                    *(float2*)&ga.Cf[z][m * 512 + n] = make_float2(v0, v1);
                }
            }
        }
    }
}

// ---------------------------------------------------------------------------
// Flash attention. Block = (b,h,64 q rows), 128 threads, 3 CTA/SM.
// Softmax in log2 domain (Q pre-scaled by 0.125*log2e; ex2.approx).
// smem/stage: Khi,Klo,Vhi,Vlo each 64x72 bf16 = 9216B -> 36864B; 2 stages.
// MMA emission: pair-buffered fragments, term-outer (same-acc distance 4).
// ---------------------------------------------------------------------------
#define ASTG 36864
#define ATTN_SMEM (2 * ASTG)
__global__ void __launch_bounds__(128, 3)
attn_kernel(const __nv_bfloat16* __restrict__ Qh_, const __nv_bfloat16* __restrict__ Ql_,
            const __nv_bfloat16* __restrict__ Kh_, const __nv_bfloat16* __restrict__ Kl_,
            const __nv_bfloat16* __restrict__ Vh_, const __nv_bfloat16* __restrict__ Vl_,
            __nv_bfloat16* __restrict__ Ch, __nv_bfloat16* __restrict__ Cl)
{
    extern __shared__ __align__(16) unsigned char dsm[];
    const unsigned smb = sptr(dsm);
    const int tid = threadIdx.x, w = tid >> 5, lane = tid & 31;
    const int q0 = blockIdx.x * 64;
    const int h = blockIdx.y, b = blockIdx.z;
    const long base = (long)((b << 3) + h) * (2048 * 64);

    // ---- Q tile (64 rows) -> smem (aliased in stage0) -> registers ----
#pragma unroll
    for (int c = 0; c < 8; c++) {
        int idx = tid + c * 128;                 // 0..1023
        int p = idx >> 9, r = (idx >> 3) & 63, q = idx & 7;
        const __nv_bfloat16* src = (p ? Ql_ : Qh_) + base + (long)(q0 + r) * 64 + q * 8;
        cpasync16(smb + p * 9216 + r * 144 + q * 16, src);
    }
    cpcommit(); cpwait<0>();
    __syncthreads();

    unsigned qh[4][4], ql[4][4];
#pragma unroll
    for (int ks = 0; ks < 4; ks++) {
        unsigned off = (w * 16 + (lane & 15)) * 144 + (ks * 16 + ((lane >> 4) << 3)) * 2;
        ldsm4(qh[ks], smb + off);
        ldsm4(ql[ks], smb + 9216 + off);
    }
    __syncthreads();

    float o[8][4];
#pragma unroll
    for (int j = 0; j < 8; j++)
#pragma unroll
        for (int i = 0; i < 4; i++) o[j][i] = 0.f;
    float rm[2] = {-1e30f, -1e30f}, rl[2] = {0.f, 0.f};

#pragma unroll 1
    for (int t = -1; t < 32; t++) {
        int lt = t + 1;
        if (lt < 32) {  // prefetch tile lt
            unsigned sdst = smb + (lt & 1) * ASTG;
            long coff = base + (long)lt * 64 * 64;
#pragma unroll
            for (int c = 0; c < 16; c++) {
                int idx = tid + c * 128;         // 0..2047
                int p = idx >> 9, r = (idx >> 3) & 63, q = idx & 7;
                const __nv_bfloat16* sp = (p == 0) ? Kh_ : (p == 1) ? Kl_
                                         : (p == 2) ? Vh_ : Vl_;
                cpasync16(sdst + p * 9216 + r * 144 + q * 16, sp + coff + r * 64 + q * 8);
            }
            cpcommit();
        }
        if (t < 0) continue;
        if (t < 31) cpwait<1>(); else cpwait<0>();
        __syncthreads();

        unsigned stb = smb + (t & 1) * ASTG;

        // ---- S = Q @ K^T (log2-domain scores); pair-buffered, term-outer ----
        float s[8][4];
#pragma unroll
        for (int j = 0; j < 8; j++)
#pragma unroll
            for (int i = 0; i < 4; i++) s[j][i] = 0.f;

#pragma unroll
        for (int ks = 0; ks < 4; ks++) {
#pragma unroll
            for (int nph = 0; nph < 2; nph++) {
                unsigned bh2[2][4], bl2[2][4];
#pragma unroll
                for (int j = 0; j < 2; j++) {
                    int np = nph * 2 + j;
                    unsigned boff = ((np * 16 + (lane & 7) + ((lane >> 4) << 3)) * 144
                                     + (ks * 16 + ((lane >> 3) & 1) * 8) * 2);
                    ldsm4(bh2[j], stb + boff);
                    ldsm4(bl2[j], stb + 9216 + boff);
                }
#pragma unroll
                for (int term = 0; term < 3; term++) {
                    const unsigned* a = (term == 2) ? ql[ks] : qh[ks];
#pragma unroll
                    for (int j = 0; j < 2; j++) {
                        int np = nph * 2 + j;
                        const unsigned* bb = (term == 1) ? bl2[j] : bh2[j];
                        mma16816(s[np * 2],     a, bb);
                        mma16816(s[np * 2 + 1], a, bb + 2);
                    }
                }
            }
        }

        // ---- online softmax (base-2) ----
#pragma unroll
        for (int rr = 0; rr < 2; rr++) {
            float mt = -1e30f;
#pragma unroll
            for (int j = 0; j < 8; j++)
                mt = fmaxf(mt, fmaxf(s[j][rr * 2], s[j][rr * 2 + 1]));
            mt = fmaxf(mt, __shfl_xor_sync(0xffffffffu, mt, 1));
            mt = fmaxf(mt, __shfl_xor_sync(0xffffffffu, mt, 2));
            float mn = fmaxf(rm[rr], mt);
            float corr = ex2(rm[rr] - mn);
            rm[rr] = mn;
            float ls = 0.f;
#pragma unroll
            for (int j = 0; j < 8; j++) {
                float p0 = ex2(s[j][rr * 2] - mn);
                float p1 = ex2(s[j][rr * 2 + 1] - mn);
                s[j][rr * 2] = p0; s[j][rr * 2 + 1] = p1;
                ls += p0 + p1;
            }
            ls += __shfl_xor_sync(0xffffffffu, ls, 1);
            ls += __shfl_xor_sync(0xffffffffu, ls, 2);
            rl[rr] = rl[rr] * corr + ls;
#pragma unroll
            for (int j = 0; j < 8; j++) {
                o[j][rr * 2] *= corr; o[j][rr * 2 + 1] *= corr;
            }
        }

        // ---- P fragments (S C-frag layout == PV A-frag layout) ----
        unsigned ph[4][4], pl[4][4];
#pragma unroll
        for (int kc = 0; kc < 4; kc++) {
            split2(s[2 * kc][0],     s[2 * kc][1],     ph[kc][0], pl[kc][0]);
            split2(s[2 * kc][2],     s[2 * kc][3],     ph[kc][1], pl[kc][1]);
            split2(s[2 * kc + 1][0], s[2 * kc + 1][1], ph[kc][2], pl[kc][2]);
            split2(s[2 * kc + 1][2], s[2 * kc + 1][3], ph[kc][3], pl[kc][3]);
        }

        // ---- O += P @ V; pair-buffered V frags, term-outer ----
#pragma unroll
        for (int ks = 0; ks < 4; ks++) {
            unsigned vrow = ks * 16 + (lane & 7) + ((lane >> 3) & 1) * 8;
#pragma unroll
            for (int dph = 0; dph < 2; dph++) {
                unsigned vh2[2][4], vl2[2][4];
#pragma unroll
                for (int j = 0; j < 2; j++) {
                    int dp = dph * 2 + j;
                    unsigned off = vrow * 144 + (dp * 16 + ((lane >> 4) << 3)) * 2;
                    ldsm4t(vh2[j], stb + 18432 + off);
                    ldsm4t(vl2[j], stb + 27648 + off);
                }
#pragma unroll
                for (int term = 0; term < 3; term++) {
                    const unsigned* a = (term == 2) ? pl[ks] : ph[ks];
#pragma unroll
                    for (int j = 0; j < 2; j++) {
                        int dp = dph * 2 + j;
                        const unsigned* bb = (term == 1) ? vl2[j] : vh2[j];
                        mma16816(o[dp * 2],     a, bb);
                        mma16816(o[dp * 2 + 1], a, bb + 2);
                    }
                }
            }
        }
        __syncthreads();
    }

    // ---- normalize, split, write ctx planes [B,S,D] ----
#pragma unroll
    for (int rr = 0; rr < 2; rr++) {
        float inv = 1.f / rl[rr];
        int rg = q0 + w * 16 + (lane >> 2) + rr * 8;
#pragma unroll
        for (int j = 0; j < 8; j++) {
            int col = h * 64 + j * 8 + (lane & 3) * 2;
            int oix = (b * 2048 + rg) * 512 + col;
            unsigned hv, lv;
            split2(o[j][rr * 2] * inv, o[j][rr * 2 + 1] * inv, hv, lv);
            *(unsigned*)&Ch[oix] = hv;
            *(unsigned*)&Cl[oix] = lv;
        }
    }
}

// ---------------------------------------------------------------------------
extern "C" void kernel_launch(void* const* d_in, const int* in_sizes, int n_in,
                              void* d_out, int out_size)
{
    const float* q  = (const float*)d_in[0];
    const float* k  = (const float*)d_in[1];
    const float* v  = (const float*)d_in[2];
    const float* Wq = (const float*)d_in[3];
    const float* bq = (const float*)d_in[4];
    const float* Wk = (const float*)d_in[5];
    const float* bk = (const float*)d_in[6];
    const float* Wv = (const float*)d_in[7];
    const float* bv = (const float*)d_in[8];
    const float* Wo = (const float*)d_in[9];
    const float* bo = (const float*)d_in[10];

    __nv_bfloat16 *qh, *ql, *kh, *kl, *vh, *vl;
    __nv_bfloat16 *wqh, *wql, *wkh, *wkl, *wvh, *wvl, *woh, *wol;
    __nv_bfloat16 *Qh, *Ql, *Kh, *Kl, *Vh, *Vl, *ch, *cl;
    cudaGetSymbolAddress((void**)&qh, g_qh);   cudaGetSymbolAddress((void**)&ql, g_ql);
    cudaGetSymbolAddress((void**)&kh, g_kh);   cudaGetSymbolAddress((void**)&kl, g_kl);
    cudaGetSymbolAddress((void**)&vh, g_vh);   cudaGetSymbolAddress((void**)&vl, g_vl);
    cudaGetSymbolAddress((void**)&wqh, g_wqh); cudaGetSymbolAddress((void**)&wql, g_wql);
    cudaGetSymbolAddress((void**)&wkh, g_wkh); cudaGetSymbolAddress((void**)&wkl, g_wkl);
    cudaGetSymbolAddress((void**)&wvh, g_wvh); cudaGetSymbolAddress((void**)&wvl, g_wvl);
    cudaGetSymbolAddress((void**)&woh, g_woh); cudaGetSymbolAddress((void**)&wol, g_wol);
    cudaGetSymbolAddress((void**)&Qh, g_Qh);   cudaGetSymbolAddress((void**)&Ql, g_Ql);
    cudaGetSymbolAddress((void**)&Kh, g_Kh);   cudaGetSymbolAddress((void**)&Kl, g_Kl);
    cudaGetSymbolAddress((void**)&Vh, g_Vh);   cudaGetSymbolAddress((void**)&Vl, g_Vl);
    cudaGetSymbolAddress((void**)&ch, g_ch);   cudaGetSymbolAddress((void**)&cl, g_cl);

    cudaFuncSetAttribute(gemm3<0>, cudaFuncAttributeMaxDynamicSharedMemorySize, G3SMEM);
    cudaFuncSetAttribute(gemm3<1>, cudaFuncAttributeMaxDynamicSharedMemorySize, G3SMEM);
    cudaFuncSetAttribute(attn_kernel, cudaFuncAttributeMaxDynamicSharedMemorySize, ATTN_SMEM);

    // 0) one convert kernel for everything
    CvtArgs ca;
    ca.src[0] = q;  ca.hi[0] = qh;  ca.lo[0] = ql;
    ca.src[1] = k;  ca.hi[1] = kh;  ca.lo[1] = kl;
    ca.src[2] = v;  ca.hi[2] = vh;  ca.lo[2] = vl;
    ca.src[3] = Wq; ca.hi[3] = wqh; ca.lo[3] = wql;
    ca.src[4] = Wk; ca.hi[4] = wkh; ca.lo[4] = wkl;
    ca.src[5] = Wv; ca.hi[5] = wvh; ca.lo[5] = wvl;
    ca.src[6] = Wo; ca.hi[6] = woh; ca.lo[6] = wol;
    convert_all<<<2048, 256>>>(ca);

    // 1) merged QKV projections (Q pre-scaled by 0.125*log2e for base-2 softmax)
    const float qscale = 0.125f * 1.44269504088896f;
    G3Args gq = {};
    gq.Ah[0] = qh; gq.Al[0] = ql; gq.Wh[0] = wqh; gq.Wl[0] = wql;
    gq.bias[0] = bq; gq.scale[0] = qscale; gq.Ch[0] = Qh; gq.Cl[0] = Ql;
    gq.Ah[1] = kh; gq.Al[1] = kl; gq.Wh[1] = wkh; gq.Wl[1] = wkl;
    gq.bias[1] = bk; gq.scale[1] = 1.0f;   gq.Ch[1] = Kh; gq.Cl[1] = Kl;
    gq.Ah[2] = vh; gq.Al[2] = vl; gq.Wh[2] = wvh; gq.Wl[2] = wvl;
    gq.bias[2] = bv; gq.scale[2] = 1.0f;   gq.Ch[2] = Vh; gq.Cl[2] = Vl;
    gemm3<1><<<dim3(4, 128, 3), 128, G3SMEM>>>(gq);

    // 2) attention: 1024 CTAs x 128 threads, 64 q-rows each
    attn_kernel<<<dim3(32, 8, 4), 128, ATTN_SMEM>>>(Qh, Ql, Kh, Kl, Vh, Vl, ch, cl);

    // 3) output projection (fp32 out + bias)
    G3Args go = {};
    go.Ah[0] = ch; go.Al[0] = cl; go.Wh[0] = woh; go.Wl[0] = wol;
    go.bias[0] = bo; go.scale[0] = 1.0f; go.Cf[0] = (float*)d_out;
    gemm3<0><<<dim3(4, 128, 1), 128, G3SMEM>>>(go);
}

// round 9
// speedup vs baseline: 1.5954x; 1.4801x over previous
#include <cuda_runtime.h>
#include <cuda_fp16.h>

// ---------------------------------------------------------------------------
// MHA, fp16 2-term split-precision mma.sync (A-side split hi+lo, B-side single
// fp16). tcgen05 unavailable (compute_103 PTX target). B=4,S=2048,D=512,H=8.
//  0) convert: q,k,v -> fp16 hi/lo; W* -> fp16 hi only
//  1) merged QKV proj GEMM: 64x128 tiles, BK=64, 128 thr, 3 CTA/SM
//     outputs: Q hi+lo (A-side of S), K hi, V hi (B-sides)
//  2) flash attn: 128 thr, 64 q-rows, 3 CTA/SM, log2 softmax, K/V single-plane
//  3) out GEMM (ctx hi+lo x Wo hi -> fp32 + bias)
// ---------------------------------------------------------------------------

#define DI __device__ __forceinline__

DI unsigned sptr(const void* p) { return (unsigned)__cvta_generic_to_shared(p); }

DI void cpasync16(unsigned dst, const void* src) {
    asm volatile("cp.async.cg.shared.global [%0], [%1], 16;" :: "r"(dst), "l"(src));
}
DI void cpcommit() { asm volatile("cp.async.commit_group;"); }
template <int N> DI void cpwait() { asm volatile("cp.async.wait_group %0;" :: "n"(N)); }

DI void ldsm4(unsigned* r, unsigned a) {
    asm volatile("ldmatrix.sync.aligned.m8n8.x4.shared.b16 {%0,%1,%2,%3}, [%4];"
                 : "=r"(r[0]), "=r"(r[1]), "=r"(r[2]), "=r"(r[3]) : "r"(a));
}
DI void ldsm4t(unsigned* r, unsigned a) {
    asm volatile("ldmatrix.sync.aligned.m8n8.x4.trans.shared.b16 {%0,%1,%2,%3}, [%4];"
                 : "=r"(r[0]), "=r"(r[1]), "=r"(r[2]), "=r"(r[3]) : "r"(a));
}
DI void mma16816(float* c, const unsigned* a, const unsigned* b) {
    asm volatile(
        "mma.sync.aligned.m16n8k16.row.col.f32.f16.f16.f32 "
        "{%0,%1,%2,%3},{%4,%5,%6,%7},{%8,%9},{%0,%1,%2,%3};"
        : "+f"(c[0]), "+f"(c[1]), "+f"(c[2]), "+f"(c[3])
        : "r"(a[0]), "r"(a[1]), "r"(a[2]), "r"(a[3]), "r"(b[0]), "r"(b[1]));
}
DI unsigned pkh(float e0, float e1) {   // pack (e0,e1) -> half2, e0 low
    __half2 h = __floats2half2_rn(e0, e1);
    return *(unsigned*)&h;
}
DI float hfr(float x) { return __half2float(__float2half_rn(x)); }
DI void split2h(float a, float b, unsigned& hi, unsigned& lo) {
    float ah = hfr(a), bh = hfr(b);
    hi = pkh(ah, bh);
    lo = pkh(a - ah, b - bh);
}
DI float ex2(float x) {
    float r; asm("ex2.approx.f32 %0, %1;" : "=f"(r) : "f"(x)); return r;
}

// ---------------- scratch (allocation-free: device globals) ----------------
#define MD (8192 * 512)
#define WD (512 * 512)
__device__ __half g_qh[MD], g_ql[MD], g_kh[MD], g_kl[MD], g_vh[MD], g_vl[MD];
__device__ __half g_wqh[WD], g_wkh[WD], g_wvh[WD], g_woh[WD];
__device__ __half g_Qh[MD], g_Ql[MD], g_Kh[MD], g_Vh[MD];
__device__ __half g_ch[MD], g_cl[MD];

// ---------------------------------------------------------------------------
// Convert: 7 tensors. s<3 (q,k,v): hi+lo planes; s>=3 (weights): hi only.
// ---------------------------------------------------------------------------
struct CvtArgs {
    const float* src[7];
    __half* hi[7];
    __half* lo[7];
};
#define MD4 (MD / 4)
#define WD4 (WD / 4)
__global__ void convert_all(CvtArgs a)
{
    const int total = 3 * MD4 + 4 * WD4;
    for (int i = blockIdx.x * blockDim.x + threadIdx.x; i < total;
         i += gridDim.x * blockDim.x) {
        int s, off;
        if (i < 3 * MD4) { s = i >> 20; off = i & (MD4 - 1); }
        else { int j = i - 3 * MD4; s = 3 + (j >> 16); off = j & (WD4 - 1); }
        float4 v = ((const float4*)a.src[s])[off];
        float hx = hfr(v.x), hy = hfr(v.y), hz = hfr(v.z), hw = hfr(v.w);
        uint2 h;
        h.x = pkh(hx, hy); h.y = pkh(hz, hw);
        ((uint2*)a.hi[s])[off] = h;
        if (s < 3) {
            uint2 l;
            l.x = pkh(v.x - hx, v.y - hy); l.y = pkh(v.z - hz, v.w - hw);
            ((uint2*)a.lo[s])[off] = l;
        }
    }
}

// ---------------------------------------------------------------------------
// GEMM: C[8192,512] = A @ W^T (+bias)(*scale). A hi+lo fp16, W hi fp16.
// Tile 64Mx128N, BK=64 (8 steps), 128 threads, warps 2(M)x2(N) = 32x64 each.
// 2-stage cp.async, 3 CTA/SM. 2-term MMA: ah*wh + al*wh.
// smem/stage: Ahi 64x144B @0, Alo @9216, Wh 128x144B @18432 -> 36864B.
// ---------------------------------------------------------------------------
#define G3STG 36864
#define G3SMEM (2 * G3STG)
struct G3Args {
    const __half* Ah[3];
    const __half* Al[3];
    const __half* Wh[3];
    const float* bias[3];
    float scale[3];
    float* Cf[3];
    __half* Ch[3];
    __half* Cl[3];   // null => single-plane fp16 output
};
template <int OUT_SPLIT>
__global__ void __launch_bounds__(128, 3)
gemm3(G3Args ga)
{
    extern __shared__ __align__(16) unsigned char dsm[];
    const unsigned smb = sptr(dsm);
    const int z = blockIdx.z;
    const __half* __restrict__ Ahi = ga.Ah[z];
    const __half* __restrict__ Alo = ga.Al[z];
    const __half* __restrict__ Whi = ga.Wh[z];
    const float* __restrict__ bias = ga.bias[z];
    const float scale = ga.scale[z];

    const int tid = threadIdx.x, w = tid >> 5, lane = tid & 31;
    const int wm = w >> 1, wn = w & 1;
    const int m0 = blockIdx.y * 64, n0 = blockIdx.x * 128;

    float acc[2][8][4];
#pragma unroll
    for (int a = 0; a < 2; a++)
#pragma unroll
        for (int b = 0; b < 8; b++)
#pragma unroll
            for (int c = 0; c < 4; c++) acc[a][b][c] = 0.f;

#pragma unroll 1
    for (int step = -1; step < 8; step++) {
        int lt = step + 1;
        if (lt < 8) {
            unsigned sdst = smb + (lt & 1) * G3STG;
            int k0 = lt * 64;
#pragma unroll
            for (int c = 0; c < 16; c++) {
                int idx = tid + c * 128;           // 0..2047
                if (idx < 1024) {                  // A: 2 planes x 64 rows x 8
                    int p = idx >> 9, r = (idx >> 3) & 63, q = idx & 7;
                    const __half* sp = p ? Alo : Ahi;
                    cpasync16(sdst + p * 9216 + r * 144 + q * 16,
                              sp + (m0 + r) * 512 + k0 + q * 8);
                } else {                           // W: 128 rows x 8
                    int j = idx - 1024;
                    int r = (j >> 3) & 127, q = j & 7;
                    cpasync16(sdst + 18432 + r * 144 + q * 16,
                              Whi + (n0 + r) * 512 + k0 + q * 8);
                }
            }
            cpcommit();
        }
        if (step < 0) continue;
        if (step < 7) cpwait<1>(); else cpwait<0>();
        __syncthreads();

        unsigned sa = smb + (step & 1) * G3STG;
#pragma unroll
        for (int ks = 0; ks < 4; ks++) {
            unsigned bh[4][4];
#pragma unroll
            for (int np = 0; np < 4; np++) {
                unsigned boff = (wn * 64 + np * 16 + (lane & 7) + ((lane >> 4) << 3)) * 144
                                + ks * 32 + ((lane >> 3) & 1) * 16;
                ldsm4(bh[np], sa + 18432 + boff);
            }
            unsigned ah[2][4], al[2][4];
#pragma unroll
            for (int mi = 0; mi < 2; mi++) {
                unsigned aoff = (wm * 32 + mi * 16 + (lane & 15)) * 144
                                + ks * 32 + (lane >> 4) * 16;
                ldsm4(ah[mi], sa + aoff);
                ldsm4(al[mi], sa + 9216 + aoff);
            }
#pragma unroll
            for (int term = 0; term < 2; term++) {
#pragma unroll
                for (int mi = 0; mi < 2; mi++) {
                    const unsigned* a = term ? al[mi] : ah[mi];
#pragma unroll
                    for (int np = 0; np < 4; np++) {
                        mma16816(acc[mi][np * 2],     a, bh[np]);
                        mma16816(acc[mi][np * 2 + 1], a, bh[np] + 2);
                    }
                }
            }
        }
        __syncthreads();
    }

    // epilogue
    const bool has_lo = OUT_SPLIT && (ga.Cl[z] != nullptr);
#pragma unroll
    for (int mi = 0; mi < 2; mi++) {
#pragma unroll
        for (int j = 0; j < 8; j++) {
            int n = n0 + wn * 64 + j * 8 + (lane & 3) * 2;
            float b0 = bias[n], b1 = bias[n + 1];
#pragma unroll
            for (int rr = 0; rr < 2; rr++) {
                int m = m0 + wm * 32 + mi * 16 + (lane >> 2) + rr * 8;
                float v0 = (acc[mi][j][rr * 2]     + b0) * scale;
                float v1 = (acc[mi][j][rr * 2 + 1] + b1) * scale;
                if (OUT_SPLIT) {
                    int bb = m >> 11, s = m & 2047, hh = n >> 6, hd = n & 63;
                    int o = (((bb << 3) + hh) * 2048 + s) * 64 + hd;
                    if (has_lo) {
                        unsigned hv, lv; split2h(v0, v1, hv, lv);
                        *(unsigned*)&ga.Ch[z][o] = hv;
                        *(unsigned*)&ga.Cl[z][o] = lv;
                    } else {
                        *(unsigned*)&ga.Ch[z][o] = pkh(v0, v1);
                    }
                } else {
                    *(float2*)&ga.Cf[z][m * 512 + n] = make_float2(v0, v1);
                }
            }
        }
    }
}

// ---------------------------------------------------------------------------
// Flash attention. Block = (b,h,64 q rows), 128 threads, 3 CTA/SM.
// Q hi+lo (A-side split), K/V single fp16 plane (B-side).
// log2-domain softmax. smem/stage: Khi 64x144B @0, Vhi @9216 -> 18432B; x2.
// Q staged once in stage0 area, then lives in registers.
// ---------------------------------------------------------------------------
#define ASTG 18432
#define ATTN_SMEM (2 * ASTG)
__global__ void __launch_bounds__(128, 3)
attn_kernel(const __half* __restrict__ Qh_, const __half* __restrict__ Ql_,
            const __half* __restrict__ Kh_, const __half* __restrict__ Vh_,
            __half* __restrict__ Ch, __half* __restrict__ Cl)
{
    extern __shared__ __align__(16) unsigned char dsm[];
    const unsigned smb = sptr(dsm);
    const int tid = threadIdx.x, w = tid >> 5, lane = tid & 31;
    const int q0 = blockIdx.x * 64;
    const int h = blockIdx.y, b = blockIdx.z;
    const long base = (long)((b << 3) + h) * (2048 * 64);

    // ---- Q tile (64 rows, hi+lo) -> smem stage0 area -> registers ----
#pragma unroll
    for (int c = 0; c < 8; c++) {
        int idx = tid + c * 128;                 // 0..1023
        int p = idx >> 9, r = (idx >> 3) & 63, q = idx & 7;
        const __half* src = (p ? Ql_ : Qh_) + base + (long)(q0 + r) * 64 + q * 8;
        cpasync16(smb + p * 9216 + r * 144 + q * 16, src);
    }
    cpcommit(); cpwait<0>();
    __syncthreads();

    unsigned qh[4][4], ql[4][4];
#pragma unroll
    for (int ks = 0; ks < 4; ks++) {
        unsigned off = (w * 16 + (lane & 15)) * 144 + ks * 32 + (lane >> 4) * 16;
        ldsm4(qh[ks], smb + off);
        ldsm4(ql[ks], smb + 9216 + off);
    }
    __syncthreads();

    float o[8][4];
#pragma unroll
    for (int j = 0; j < 8; j++)
#pragma unroll
        for (int i = 0; i < 4; i++) o[j][i] = 0.f;
    float rm[2] = {-1e30f, -1e30f}, rl[2] = {0.f, 0.f};

#pragma unroll 1
    for (int t = -1; t < 32; t++) {
        int lt = t + 1;
        if (lt < 32) {  // prefetch K/V tile lt (single planes)
            unsigned sdst = smb + (lt & 1) * ASTG;
            long coff = base + (long)lt * 64 * 64;
#pragma unroll
            for (int c = 0; c < 8; c++) {
                int idx = tid + c * 128;         // 0..1023
                int p = idx >> 9, r = (idx >> 3) & 63, q = idx & 7;
                const __half* sp = p ? Vh_ : Kh_;
                cpasync16(sdst + p * 9216 + r * 144 + q * 16, sp + coff + r * 64 + q * 8);
            }
            cpcommit();
        }
        if (t < 0) continue;
        if (t < 31) cpwait<1>(); else cpwait<0>();
        __syncthreads();

        unsigned stb = smb + (t & 1) * ASTG;

        // ---- S = Q @ K^T (log2-domain scores), 2-term: qh*kh + ql*kh ----
        float s[8][4];
#pragma unroll
        for (int j = 0; j < 8; j++)
#pragma unroll
            for (int i = 0; i < 4; i++) s[j][i] = 0.f;

#pragma unroll
        for (int ks = 0; ks < 4; ks++) {
            unsigned kh[4][4];
#pragma unroll
            for (int np = 0; np < 4; np++) {
                unsigned boff = (np * 16 + (lane & 7) + ((lane >> 4) << 3)) * 144
                                + ks * 32 + ((lane >> 3) & 1) * 16;
                ldsm4(kh[np], stb + boff);
            }
#pragma unroll
            for (int term = 0; term < 2; term++) {
                const unsigned* a = term ? ql[ks] : qh[ks];
#pragma unroll
                for (int np = 0; np < 4; np++) {
                    mma16816(s[np * 2],     a, kh[np]);
                    mma16816(s[np * 2 + 1], a, kh[np] + 2);
                }
            }
        }

        // ---- online softmax (base-2) ----
#pragma unroll
        for (int rr = 0; rr < 2; rr++) {
            float mt = -1e30f;
#pragma unroll
            for (int j = 0; j < 8; j++)
                mt = fmaxf(mt, fmaxf(s[j][rr * 2], s[j][rr * 2 + 1]));
            mt = fmaxf(mt, __shfl_xor_sync(0xffffffffu, mt, 1));
            mt = fmaxf(mt, __shfl_xor_sync(0xffffffffu, mt, 2));
            float mn = fmaxf(rm[rr], mt);
            float corr = ex2(rm[rr] - mn);
            rm[rr] = mn;
            float ls = 0.f;
#pragma unroll
            for (int j = 0; j < 8; j++) {
                float p0 = ex2(s[j][rr * 2] - mn);
                float p1 = ex2(s[j][rr * 2 + 1] - mn);
                s[j][rr * 2] = p0; s[j][rr * 2 + 1] = p1;
                ls += p0 + p1;
            }
            ls += __shfl_xor_sync(0xffffffffu, ls, 1);
            ls += __shfl_xor_sync(0xffffffffu, ls, 2);
            rl[rr] = rl[rr] * corr + ls;
#pragma unroll
            for (int j = 0; j < 8; j++) {
                o[j][rr * 2] *= corr; o[j][rr * 2 + 1] *= corr;
            }
        }

        // ---- P fragments hi+lo (S C-frag layout == PV A-frag layout) ----
        unsigned ph[4][4], pl[4][4];
#pragma unroll
        for (int kc = 0; kc < 4; kc++) {
            split2h(s[2 * kc][0],     s[2 * kc][1],     ph[kc][0], pl[kc][0]);
            split2h(s[2 * kc][2],     s[2 * kc][3],     ph[kc][1], pl[kc][1]);
            split2h(s[2 * kc + 1][0], s[2 * kc + 1][1], ph[kc][2], pl[kc][2]);
            split2h(s[2 * kc + 1][2], s[2 * kc + 1][3], ph[kc][3], pl[kc][3]);
        }

        // ---- O += P @ V, 2-term: ph*vh + pl*vh ----
#pragma unroll
        for (int ks = 0; ks < 4; ks++) {
            unsigned vrow = ks * 16 + (lane & 7) + ((lane >> 3) & 1) * 8;
            unsigned vh[4][4];
#pragma unroll
            for (int dp = 0; dp < 4; dp++) {
                unsigned off = vrow * 144 + dp * 32 + (lane >> 4) * 16;
                ldsm4t(vh[dp], stb + 9216 + off);
            }
#pragma unroll
            for (int term = 0; term < 2; term++) {
                const unsigned* a = term ? pl[ks] : ph[ks];
#pragma unroll
                for (int dp = 0; dp < 4; dp++) {
                    mma16816(o[dp * 2],     a, vh[dp]);
                    mma16816(o[dp * 2 + 1], a, vh[dp] + 2);
                }
            }
        }
        __syncthreads();
    }

    // ---- normalize, split, write ctx hi+lo planes [B,S,D] ----
#pragma unroll
    for (int rr = 0; rr < 2; rr++) {
        float inv = 1.f / rl[rr];
        int rg = q0 + w * 16 + (lane >> 2) + rr * 8;
#pragma unroll
        for (int j = 0; j < 8; j++) {
            int col = h * 64 + j * 8 + (lane & 3) * 2;
            int oix = (b * 2048 + rg) * 512 + col;
            unsigned hv, lv;
            split2h(o[j][rr * 2] * inv, o[j][rr * 2 + 1] * inv, hv, lv);
            *(unsigned*)&Ch[oix] = hv;
            *(unsigned*)&Cl[oix] = lv;
        }
    }
}

// ---------------------------------------------------------------------------
extern "C" void kernel_launch(void* const* d_in, const int* in_sizes, int n_in,
                              void* d_out, int out_size)
{
    const float* q  = (const float*)d_in[0];
    const float* k  = (const float*)d_in[1];
    const float* v  = (const float*)d_in[2];
    const float* Wq = (const float*)d_in[3];
    const float* bq = (const float*)d_in[4];
    const float* Wk = (const float*)d_in[5];
    const float* bk = (const float*)d_in[6];
    const float* Wv = (const float*)d_in[7];
    const float* bv = (const float*)d_in[8];
    const float* Wo = (const float*)d_in[9];
    const float* bo = (const float*)d_in[10];

    __half *qh, *ql, *kh, *kl, *vh, *vl;
    __half *wqh, *wkh, *wvh, *woh;
    __half *Qh, *Ql, *Kh, *Vh, *ch, *cl;
    cudaGetSymbolAddress((void**)&qh, g_qh);   cudaGetSymbolAddress((void**)&ql, g_ql);
    cudaGetSymbolAddress((void**)&kh, g_kh);   cudaGetSymbolAddress((void**)&kl, g_kl);
    cudaGetSymbolAddress((void**)&vh, g_vh);   cudaGetSymbolAddress((void**)&vl, g_vl);
    cudaGetSymbolAddress((void**)&wqh, g_wqh); cudaGetSymbolAddress((void**)&wkh, g_wkh);
    cudaGetSymbolAddress((void**)&wvh, g_wvh); cudaGetSymbolAddress((void**)&woh, g_woh);
    cudaGetSymbolAddress((void**)&Qh, g_Qh);   cudaGetSymbolAddress((void**)&Ql, g_Ql);
    cudaGetSymbolAddress((void**)&Kh, g_Kh);   cudaGetSymbolAddress((void**)&Vh, g_Vh);
    cudaGetSymbolAddress((void**)&ch, g_ch);   cudaGetSymbolAddress((void**)&cl, g_cl);

    cudaFuncSetAttribute(gemm3<0>, cudaFuncAttributeMaxDynamicSharedMemorySize, G3SMEM);
    cudaFuncSetAttribute(gemm3<1>, cudaFuncAttributeMaxDynamicSharedMemorySize, G3SMEM);
    cudaFuncSetAttribute(attn_kernel, cudaFuncAttributeMaxDynamicSharedMemorySize, ATTN_SMEM);

    // 0) one convert kernel for everything
    CvtArgs ca = {};
    ca.src[0] = q;  ca.hi[0] = qh;  ca.lo[0] = ql;
    ca.src[1] = k;  ca.hi[1] = kh;  ca.lo[1] = kl;
    ca.src[2] = v;  ca.hi[2] = vh;  ca.lo[2] = vl;
    ca.src[3] = Wq; ca.hi[3] = wqh;
    ca.src[4] = Wk; ca.hi[4] = wkh;
    ca.src[5] = Wv; ca.hi[5] = wvh;
    ca.src[6] = Wo; ca.hi[6] = woh;
    convert_all<<<2048, 256>>>(ca);

    // 1) merged QKV projections (Q pre-scaled by 0.125*log2e for base-2 softmax)
    const float qscale = 0.125f * 1.44269504088896f;
    G3Args gq = {};
    gq.Ah[0] = qh; gq.Al[0] = ql; gq.Wh[0] = wqh;
    gq.bias[0] = bq; gq.scale[0] = qscale; gq.Ch[0] = Qh; gq.Cl[0] = Ql;
    gq.Ah[1] = kh; gq.Al[1] = kl; gq.Wh[1] = wkh;
    gq.bias[1] = bk; gq.scale[1] = 1.0f;   gq.Ch[1] = Kh; gq.Cl[1] = nullptr;
    gq.Ah[2] = vh; gq.Al[2] = vl; gq.Wh[2] = wvh;
    gq.bias[2] = bv; gq.scale[2] = 1.0f;   gq.Ch[2] = Vh; gq.Cl[2] = nullptr;
    gemm3<1><<<dim3(4, 128, 3), 128, G3SMEM>>>(gq);

    // 2) attention: 1024 CTAs x 128 threads, 64 q-rows each
    attn_kernel<<<dim3(32, 8, 4), 128, ATTN_SMEM>>>(Qh, Ql, Kh, Vh, ch, cl);

    // 3) output projection (fp32 out + bias)
    G3Args go = {};
    go.Ah[0] = ch; go.Al[0] = cl; go.Wh[0] = woh;
    go.bias[0] = bo; go.scale[0] = 1.0f; go.Cf[0] = (float*)d_out;
    gemm3<0><<<dim3(4, 128, 1), 128, G3SMEM>>>(go);
}

// round 10
// speedup vs baseline: 1.8628x; 1.1676x over previous
#include <cuda_runtime.h>
#include <cuda_fp16.h>

// ---------------------------------------------------------------------------
// MHA, fp16 split-precision mma.sync (HMMA issue ceiling ~683 MAC/cyc/SM is
// the binding constraint; tcgen05 unavailable under compute_103 PTX target).
// B=4, S=2048, D=512, H=8, HD=64.
//  0) convert: q,k,v -> fp16 hi/lo; W* -> fp16 hi only
//  1) merged QKV proj GEMM (2-term: A split, W single), 3 CTA/SM
//  2) flash attn: S 2-term (Q split), PV 1-term (P single), ctx single plane
//  3) out GEMM 1-term (ctx single x Wo single -> fp32 + bias)
// Error stack (RMS, validated): 4xW-round 5.2e-4 + P-round 2.8e-4 +
// ctx-round 2.8e-4 => ~6.5e-4 < 1e-3.
// ---------------------------------------------------------------------------

#define DI __device__ __forceinline__

DI unsigned sptr(const void* p) { return (unsigned)__cvta_generic_to_shared(p); }

DI void cpasync16(unsigned dst, const void* src) {
    asm volatile("cp.async.cg.shared.global [%0], [%1], 16;" :: "r"(dst), "l"(src));
}
DI void cpcommit() { asm volatile("cp.async.commit_group;"); }
template <int N> DI void cpwait() { asm volatile("cp.async.wait_group %0;" :: "n"(N)); }

DI void ldsm4(unsigned* r, unsigned a) {
    asm volatile("ldmatrix.sync.aligned.m8n8.x4.shared.b16 {%0,%1,%2,%3}, [%4];"
                 : "=r"(r[0]), "=r"(r[1]), "=r"(r[2]), "=r"(r[3]) : "r"(a));
}
DI void ldsm4t(unsigned* r, unsigned a) {
    asm volatile("ldmatrix.sync.aligned.m8n8.x4.trans.shared.b16 {%0,%1,%2,%3}, [%4];"
                 : "=r"(r[0]), "=r"(r[1]), "=r"(r[2]), "=r"(r[3]) : "r"(a));
}
DI void mma16816(float* c, const unsigned* a, const unsigned* b) {
    asm volatile(
        "mma.sync.aligned.m16n8k16.row.col.f32.f16.f16.f32 "
        "{%0,%1,%2,%3},{%4,%5,%6,%7},{%8,%9},{%0,%1,%2,%3};"
        : "+f"(c[0]), "+f"(c[1]), "+f"(c[2]), "+f"(c[3])
        : "r"(a[0]), "r"(a[1]), "r"(a[2]), "r"(a[3]), "r"(b[0]), "r"(b[1]));
}
DI unsigned pkh(float e0, float e1) {   // pack (e0,e1) -> half2, e0 low
    __half2 h = __floats2half2_rn(e0, e1);
    return *(unsigned*)&h;
}
DI float hfr(float x) { return __half2float(__float2half_rn(x)); }
DI void split2h(float a, float b, unsigned& hi, unsigned& lo) {
    float ah = hfr(a), bh = hfr(b);
    hi = pkh(ah, bh);
    lo = pkh(a - ah, b - bh);
}
DI float ex2(float x) {
    float r; asm("ex2.approx.f32 %0, %1;" : "=f"(r) : "f"(x)); return r;
}

// ---------------- scratch (allocation-free: device globals) ----------------
#define MD (8192 * 512)
#define WD (512 * 512)
__device__ __half g_qh[MD], g_ql[MD], g_kh[MD], g_kl[MD], g_vh[MD], g_vl[MD];
__device__ __half g_wqh[WD], g_wkh[WD], g_wvh[WD], g_woh[WD];
__device__ __half g_Qh[MD], g_Ql[MD], g_Kh[MD], g_Vh[MD];
__device__ __half g_ch[MD];

// ---------------------------------------------------------------------------
// Convert: 7 tensors. s<3 (q,k,v): hi+lo planes; s>=3 (weights): hi only.
// ---------------------------------------------------------------------------
struct CvtArgs {
    const float* src[7];
    __half* hi[7];
    __half* lo[7];
};
#define MD4 (MD / 4)
#define WD4 (WD / 4)
__global__ void convert_all(CvtArgs a)
{
    const int total = 3 * MD4 + 4 * WD4;
    for (int i = blockIdx.x * blockDim.x + threadIdx.x; i < total;
         i += gridDim.x * blockDim.x) {
        int s, off;
        if (i < 3 * MD4) { s = i >> 20; off = i & (MD4 - 1); }
        else { int j = i - 3 * MD4; s = 3 + (j >> 16); off = j & (WD4 - 1); }
        float4 v = ((const float4*)a.src[s])[off];
        float hx = hfr(v.x), hy = hfr(v.y), hz = hfr(v.z), hw = hfr(v.w);
        uint2 h;
        h.x = pkh(hx, hy); h.y = pkh(hz, hw);
        ((uint2*)a.hi[s])[off] = h;
        if (s < 3) {
            uint2 l;
            l.x = pkh(v.x - hx, v.y - hy); l.y = pkh(v.z - hz, v.w - hw);
            ((uint2*)a.lo[s])[off] = l;
        }
    }
}

// ---------------------------------------------------------------------------
// GEMM: C[8192,512] = A @ W^T (+bias)(*scale). NTERM=2: A hi+lo; NTERM=1: A hi.
// Tile 64Mx128N, BK=64 (8 steps), 128 threads, warps 2(M)x2(N) = 32x64 each.
// 2-stage cp.async, 3 CTA/SM.
// smem/stage: Ahi 64x144B @0, (Alo @9216 if NTERM=2), Wh 128x144B @18432.
// ---------------------------------------------------------------------------
#define G3STG 36864
#define G3SMEM (2 * G3STG)
struct G3Args {
    const __half* Ah[3];
    const __half* Al[3];
    const __half* Wh[3];
    const float* bias[3];
    float scale[3];
    float* Cf[3];
    __half* Ch[3];
    __half* Cl[3];   // null => single-plane fp16 output
};
template <int OUT_SPLIT, int NTERM>
__global__ void __launch_bounds__(128, 3)
gemm3(G3Args ga)
{
    extern __shared__ __align__(16) unsigned char dsm[];
    const unsigned smb = sptr(dsm);
    const int z = blockIdx.z;
    const __half* __restrict__ Ahi = ga.Ah[z];
    const __half* __restrict__ Alo = ga.Al[z];
    const __half* __restrict__ Whi = ga.Wh[z];
    const float* __restrict__ bias = ga.bias[z];
    const float scale = ga.scale[z];

    const int tid = threadIdx.x, w = tid >> 5, lane = tid & 31;
    const int wm = w >> 1, wn = w & 1;
    const int m0 = blockIdx.y * 64, n0 = blockIdx.x * 128;

    float acc[2][8][4];
#pragma unroll
    for (int a = 0; a < 2; a++)
#pragma unroll
        for (int b = 0; b < 8; b++)
#pragma unroll
            for (int c = 0; c < 4; c++) acc[a][b][c] = 0.f;

#pragma unroll 1
    for (int step = -1; step < 8; step++) {
        int lt = step + 1;
        if (lt < 8) {
            unsigned sdst = smb + (lt & 1) * G3STG;
            int k0 = lt * 64;
#pragma unroll
            for (int c = 0; c < 16; c++) {
                int idx = tid + c * 128;           // 0..2047
                if (idx < 1024) {                  // A: up to 2 planes x 64 x 8
                    int p = idx >> 9, r = (idx >> 3) & 63, q = idx & 7;
                    if (NTERM == 2 || p == 0) {
                        const __half* sp = p ? Alo : Ahi;
                        cpasync16(sdst + p * 9216 + r * 144 + q * 16,
                                  sp + (m0 + r) * 512 + k0 + q * 8);
                    }
                } else {                           // W: 128 rows x 8
                    int j = idx - 1024;
                    int r = (j >> 3) & 127, q = j & 7;
                    cpasync16(sdst + 18432 + r * 144 + q * 16,
                              Whi + (n0 + r) * 512 + k0 + q * 8);
                }
            }
            cpcommit();
        }
        if (step < 0) continue;
        if (step < 7) cpwait<1>(); else cpwait<0>();
        __syncthreads();

        unsigned sa = smb + (step & 1) * G3STG;
#pragma unroll
        for (int ks = 0; ks < 4; ks++) {
            unsigned bh[4][4];
#pragma unroll
            for (int np = 0; np < 4; np++) {
                unsigned boff = (wn * 64 + np * 16 + (lane & 7) + ((lane >> 4) << 3)) * 144
                                + ks * 32 + ((lane >> 3) & 1) * 16;
                ldsm4(bh[np], sa + 18432 + boff);
            }
            unsigned ah[2][4], al[2][4];
#pragma unroll
            for (int mi = 0; mi < 2; mi++) {
                unsigned aoff = (wm * 32 + mi * 16 + (lane & 15)) * 144
                                + ks * 32 + (lane >> 4) * 16;
                ldsm4(ah[mi], sa + aoff);
                if (NTERM == 2) ldsm4(al[mi], sa + 9216 + aoff);
            }
#pragma unroll
            for (int term = 0; term < NTERM; term++) {
#pragma unroll
                for (int mi = 0; mi < 2; mi++) {
                    const unsigned* a = term ? al[mi] : ah[mi];
#pragma unroll
                    for (int np = 0; np < 4; np++) {
                        mma16816(acc[mi][np * 2],     a, bh[np]);
                        mma16816(acc[mi][np * 2 + 1], a, bh[np] + 2);
                    }
                }
            }
        }
        __syncthreads();
    }

    // epilogue
    const bool has_lo = OUT_SPLIT && (ga.Cl[z] != nullptr);
#pragma unroll
    for (int mi = 0; mi < 2; mi++) {
#pragma unroll
        for (int j = 0; j < 8; j++) {
            int n = n0 + wn * 64 + j * 8 + (lane & 3) * 2;
            float b0 = bias[n], b1 = bias[n + 1];
#pragma unroll
            for (int rr = 0; rr < 2; rr++) {
                int m = m0 + wm * 32 + mi * 16 + (lane >> 2) + rr * 8;
                float v0 = (acc[mi][j][rr * 2]     + b0) * scale;
                float v1 = (acc[mi][j][rr * 2 + 1] + b1) * scale;
                if (OUT_SPLIT) {
                    int bb = m >> 11, s = m & 2047, hh = n >> 6, hd = n & 63;
                    int o = (((bb << 3) + hh) * 2048 + s) * 64 + hd;
                    if (has_lo) {
                        unsigned hv, lv; split2h(v0, v1, hv, lv);
                        *(unsigned*)&ga.Ch[z][o] = hv;
                        *(unsigned*)&ga.Cl[z][o] = lv;
                    } else {
                        *(unsigned*)&ga.Ch[z][o] = pkh(v0, v1);
                    }
                } else {
                    *(float2*)&ga.Cf[z][m * 512 + n] = make_float2(v0, v1);
                }
            }
        }
    }
}

// ---------------------------------------------------------------------------
// Flash attention. Block = (b,h,64 q rows), 128 threads, 3 CTA/SM.
// S: Q hi+lo (2-term) x K single. PV: P single (1-term) x V single.
// ctx written as single fp16 plane. log2-domain softmax.
// smem/stage: Kh 64x144B @0, Vh @9216 -> 18432B; 2 stages.
// ---------------------------------------------------------------------------
#define ASTG 18432
#define ATTN_SMEM (2 * ASTG)
__global__ void __launch_bounds__(128, 3)
attn_kernel(const __half* __restrict__ Qh_, const __half* __restrict__ Ql_,
            const __half* __restrict__ Kh_, const __half* __restrict__ Vh_,
            __half* __restrict__ Ch)
{
    extern __shared__ __align__(16) unsigned char dsm[];
    const unsigned smb = sptr(dsm);
    const int tid = threadIdx.x, w = tid >> 5, lane = tid & 31;
    const int q0 = blockIdx.x * 64;
    const int h = blockIdx.y, b = blockIdx.z;
    const long base = (long)((b << 3) + h) * (2048 * 64);

    // ---- Q tile (64 rows, hi+lo) -> smem stage0 area -> registers ----
#pragma unroll
    for (int c = 0; c < 8; c++) {
        int idx = tid + c * 128;                 // 0..1023
        int p = idx >> 9, r = (idx >> 3) & 63, q = idx & 7;
        const __half* src = (p ? Ql_ : Qh_) + base + (long)(q0 + r) * 64 + q * 8;
        cpasync16(smb + p * 9216 + r * 144 + q * 16, src);
    }
    cpcommit(); cpwait<0>();
    __syncthreads();

    unsigned qh[4][4], ql[4][4];
#pragma unroll
    for (int ks = 0; ks < 4; ks++) {
        unsigned off = (w * 16 + (lane & 15)) * 144 + ks * 32 + (lane >> 4) * 16;
        ldsm4(qh[ks], smb + off);
        ldsm4(ql[ks], smb + 9216 + off);
    }
    __syncthreads();

    float o[8][4];
#pragma unroll
    for (int j = 0; j < 8; j++)
#pragma unroll
        for (int i = 0; i < 4; i++) o[j][i] = 0.f;
    float rm[2] = {-1e30f, -1e30f}, rl[2] = {0.f, 0.f};

#pragma unroll 1
    for (int t = -1; t < 32; t++) {
        int lt = t + 1;
        if (lt < 32) {  // prefetch K/V tile lt (single planes)
            unsigned sdst = smb + (lt & 1) * ASTG;
            long coff = base + (long)lt * 64 * 64;
#pragma unroll
            for (int c = 0; c < 8; c++) {
                int idx = tid + c * 128;         // 0..1023
                int p = idx >> 9, r = (idx >> 3) & 63, q = idx & 7;
                const __half* sp = p ? Vh_ : Kh_;
                cpasync16(sdst + p * 9216 + r * 144 + q * 16, sp + coff + r * 64 + q * 8);
            }
            cpcommit();
        }
        if (t < 0) continue;
        if (t < 31) cpwait<1>(); else cpwait<0>();
        __syncthreads();

        unsigned stb = smb + (t & 1) * ASTG;

        // ---- S = Q @ K^T (log2-domain scores), 2-term: qh*kh + ql*kh ----
        float s[8][4];
#pragma unroll
        for (int j = 0; j < 8; j++)
#pragma unroll
            for (int i = 0; i < 4; i++) s[j][i] = 0.f;

#pragma unroll
        for (int ks = 0; ks < 4; ks++) {
            unsigned kh[4][4];
#pragma unroll
            for (int np = 0; np < 4; np++) {
                unsigned boff = (np * 16 + (lane & 7) + ((lane >> 4) << 3)) * 144
                                + ks * 32 + ((lane >> 3) & 1) * 16;
                ldsm4(kh[np], stb + boff);
            }
#pragma unroll
            for (int term = 0; term < 2; term++) {
                const unsigned* a = term ? ql[ks] : qh[ks];
#pragma unroll
                for (int np = 0; np < 4; np++) {
                    mma16816(s[np * 2],     a, kh[np]);
                    mma16816(s[np * 2 + 1], a, kh[np] + 2);
                }
            }
        }

        // ---- online softmax (base-2) ----
#pragma unroll
        for (int rr = 0; rr < 2; rr++) {
            float mt = -1e30f;
#pragma unroll
            for (int j = 0; j < 8; j++)
                mt = fmaxf(mt, fmaxf(s[j][rr * 2], s[j][rr * 2 + 1]));
            mt = fmaxf(mt, __shfl_xor_sync(0xffffffffu, mt, 1));
            mt = fmaxf(mt, __shfl_xor_sync(0xffffffffu, mt, 2));
            float mn = fmaxf(rm[rr], mt);
            float corr = ex2(rm[rr] - mn);
            rm[rr] = mn;
            float ls = 0.f;
#pragma unroll
            for (int j = 0; j < 8; j++) {
                float p0 = ex2(s[j][rr * 2] - mn);
                float p1 = ex2(s[j][rr * 2 + 1] - mn);
                s[j][rr * 2] = p0; s[j][rr * 2 + 1] = p1;
                ls += p0 + p1;
            }
            ls += __shfl_xor_sync(0xffffffffu, ls, 1);
            ls += __shfl_xor_sync(0xffffffffu, ls, 2);
            rl[rr] = rl[rr] * corr + ls;
#pragma unroll
            for (int j = 0; j < 8; j++) {
                o[j][rr * 2] *= corr; o[j][rr * 2 + 1] *= corr;
            }
        }

        // ---- P fragments, single fp16 (S C-frag layout == PV A-frag layout) ----
        unsigned ph[4][4];
#pragma unroll
        for (int kc = 0; kc < 4; kc++) {
            ph[kc][0] = pkh(s[2 * kc][0],     s[2 * kc][1]);
            ph[kc][1] = pkh(s[2 * kc][2],     s[2 * kc][3]);
            ph[kc][2] = pkh(s[2 * kc + 1][0], s[2 * kc + 1][1]);
            ph[kc][3] = pkh(s[2 * kc + 1][2], s[2 * kc + 1][3]);
        }

        // ---- O += P @ V, 1-term ----
#pragma unroll
        for (int ks = 0; ks < 4; ks++) {
            unsigned vrow = ks * 16 + (lane & 7) + ((lane >> 3) & 1) * 8;
#pragma unroll
            for (int dp = 0; dp < 4; dp++) {
                unsigned vh[4];
                unsigned off = vrow * 144 + dp * 32 + (lane >> 4) * 16;
                ldsm4t(vh, stb + 9216 + off);
                mma16816(o[dp * 2],     ph[ks], vh);
                mma16816(o[dp * 2 + 1], ph[ks], vh + 2);
            }
        }
        __syncthreads();
    }

    // ---- normalize, write ctx single fp16 plane [B,S,D] ----
#pragma unroll
    for (int rr = 0; rr < 2; rr++) {
        float inv = 1.f / rl[rr];
        int rg = q0 + w * 16 + (lane >> 2) + rr * 8;
#pragma unroll
        for (int j = 0; j < 8; j++) {
            int col = h * 64 + j * 8 + (lane & 3) * 2;
            int oix = (b * 2048 + rg) * 512 + col;
            *(unsigned*)&Ch[oix] = pkh(o[j][rr * 2] * inv, o[j][rr * 2 + 1] * inv);
        }
    }
}

// ---------------------------------------------------------------------------
extern "C" void kernel_launch(void* const* d_in, const int* in_sizes, int n_in,
                              void* d_out, int out_size)
{
    const float* q  = (const float*)d_in[0];
    const float* k  = (const float*)d_in[1];
    const float* v  = (const float*)d_in[2];
    const float* Wq = (const float*)d_in[3];
    const float* bq = (const float*)d_in[4];
    const float* Wk = (const float*)d_in[5];
    const float* bk = (const float*)d_in[6];
    const float* Wv = (const float*)d_in[7];
    const float* bv = (const float*)d_in[8];
    const float* Wo = (const float*)d_in[9];
    const float* bo = (const float*)d_in[10];

    __half *qh, *ql, *kh, *kl, *vh, *vl;
    __half *wqh, *wkh, *wvh, *woh;
    __half *Qh, *Ql, *Kh, *Vh, *ch;
    cudaGetSymbolAddress((void**)&qh, g_qh);   cudaGetSymbolAddress((void**)&ql, g_ql);
    cudaGetSymbolAddress((void**)&kh, g_kh);   cudaGetSymbolAddress((void**)&kl, g_kl);
    cudaGetSymbolAddress((void**)&vh, g_vh);   cudaGetSymbolAddress((void**)&vl, g_vl);
    cudaGetSymbolAddress((void**)&wqh, g_wqh); cudaGetSymbolAddress((void**)&wkh, g_wkh);
    cudaGetSymbolAddress((void**)&wvh, g_wvh); cudaGetSymbolAddress((void**)&woh, g_woh);
    cudaGetSymbolAddress((void**)&Qh, g_Qh);   cudaGetSymbolAddress((void**)&Ql, g_Ql);
    cudaGetSymbolAddress((void**)&Kh, g_Kh);   cudaGetSymbolAddress((void**)&Vh, g_Vh);
    cudaGetSymbolAddress((void**)&ch, g_ch);

    cudaFuncSetAttribute((const void*)gemm3<0, 1>,
                         cudaFuncAttributeMaxDynamicSharedMemorySize, G3SMEM);
    cudaFuncSetAttribute((const void*)gemm3<1, 2>,
                         cudaFuncAttributeMaxDynamicSharedMemorySize, G3SMEM);
    cudaFuncSetAttribute(attn_kernel, cudaFuncAttributeMaxDynamicSharedMemorySize, ATTN_SMEM);

    // 0) one convert kernel for everything
    CvtArgs ca = {};
    ca.src[0] = q;  ca.hi[0] = qh;  ca.lo[0] = ql;
    ca.src[1] = k;  ca.hi[1] = kh;  ca.lo[1] = kl;
    ca.src[2] = v;  ca.hi[2] = vh;  ca.lo[2] = vl;
    ca.src[3] = Wq; ca.hi[3] = wqh;
    ca.src[4] = Wk; ca.hi[4] = wkh;
    ca.src[5] = Wv; ca.hi[5] = wvh;
    ca.src[6] = Wo; ca.hi[6] = woh;
    convert_all<<<2048, 256>>>(ca);

    // 1) merged QKV projections (Q pre-scaled by 0.125*log2e for base-2 softmax)
    const float qscale = 0.125f * 1.44269504088896f;
    G3Args gq = {};
    gq.Ah[0] = qh; gq.Al[0] = ql; gq.Wh[0] = wqh;
    gq.bias[0] = bq; gq.scale[0] = qscale; gq.Ch[0] = Qh; gq.Cl[0] = Ql;
    gq.Ah[1] = kh; gq.Al[1] = kl; gq.Wh[1] = wkh;
    gq.bias[1] = bk; gq.scale[1] = 1.0f;   gq.Ch[1] = Kh; gq.Cl[1] = nullptr;
    gq.Ah[2] = vh; gq.Al[2] = vl; gq.Wh[2] = wvh;
    gq.bias[2] = bv; gq.scale[2] = 1.0f;   gq.Ch[2] = Vh; gq.Cl[2] = nullptr;
    gemm3<1, 2><<<dim3(4, 128, 3), 128, G3SMEM>>>(gq);

    // 2) attention: 1024 CTAs x 128 threads, 64 q-rows each
    attn_kernel<<<dim3(32, 8, 4), 128, ATTN_SMEM>>>(Qh, Ql, Kh, Vh, ch);

    // 3) output projection, 1-term (fp32 out + bias)
    G3Args go = {};
    go.Ah[0] = ch; go.Al[0] = nullptr; go.Wh[0] = woh;
    go.bias[0] = bo; go.scale[0] = 1.0f; go.Cf[0] = (float*)d_out;
    gemm3<0, 1><<<dim3(4, 128, 1), 128, G3SMEM>>>(go);
}

// round 11
// speedup vs baseline: 2.0239x; 1.0864x over previous
#include <cuda_runtime.h>
#include <cuda_fp16.h>

// ---------------------------------------------------------------------------
// MHA, fp16 mma.sync. GEMMs are L2-BW-bound -> big tiles for W/A reuse.
// B=4, S=2048, D=512, H=8, HD=64.
//  0) convert: q,k,v,W* -> single fp16 plane each
//  1) merged QKV proj GEMM (1-term), 128x128 tiles, 256 thr, 2 CTA/SM
//     Q output split hi+lo (protects softmax logits); K,V single plane
//  2) flash attn: S 2-term (Q split), PV 1-term, 128 thr, 64 q-rows, 3 CTA/SM
//  3) out GEMM 1-term (ctx single x Wo single -> fp32 + bias), single wave
// Error stack (RMS, validated model): 4xW + P + ctx + q,k,v inputs
//   = 9 terms x ~2.7e-4 -> ~7.4e-4 < 1e-3.
// ---------------------------------------------------------------------------

#define DI __device__ __forceinline__

DI unsigned sptr(const void* p) { return (unsigned)__cvta_generic_to_shared(p); }

DI void cpasync16(unsigned dst, const void* src) {
    asm volatile("cp.async.cg.shared.global [%0], [%1], 16;" :: "r"(dst), "l"(src));
}
DI void cpcommit() { asm volatile("cp.async.commit_group;"); }
template <int N> DI void cpwait() { asm volatile("cp.async.wait_group %0;" :: "n"(N)); }

DI void ldsm4(unsigned* r, unsigned a) {
    asm volatile("ldmatrix.sync.aligned.m8n8.x4.shared.b16 {%0,%1,%2,%3}, [%4];"
                 : "=r"(r[0]), "=r"(r[1]), "=r"(r[2]), "=r"(r[3]) : "r"(a));
}
DI void ldsm4t(unsigned* r, unsigned a) {
    asm volatile("ldmatrix.sync.aligned.m8n8.x4.trans.shared.b16 {%0,%1,%2,%3}, [%4];"
                 : "=r"(r[0]), "=r"(r[1]), "=r"(r[2]), "=r"(r[3]) : "r"(a));
}
DI void mma16816(float* c, const unsigned* a, const unsigned* b) {
    asm volatile(
        "mma.sync.aligned.m16n8k16.row.col.f32.f16.f16.f32 "
        "{%0,%1,%2,%3},{%4,%5,%6,%7},{%8,%9},{%0,%1,%2,%3};"
        : "+f"(c[0]), "+f"(c[1]), "+f"(c[2]), "+f"(c[3])
        : "r"(a[0]), "r"(a[1]), "r"(a[2]), "r"(a[3]), "r"(b[0]), "r"(b[1]));
}
DI unsigned pkh(float e0, float e1) {   // pack (e0,e1) -> half2, e0 low
    __half2 h = __floats2half2_rn(e0, e1);
    return *(unsigned*)&h;
}
DI float hfr(float x) { return __half2float(__float2half_rn(x)); }
DI void split2h(float a, float b, unsigned& hi, unsigned& lo) {
    float ah = hfr(a), bh = hfr(b);
    hi = pkh(ah, bh);
    lo = pkh(a - ah, b - bh);
}
DI float ex2(float x) {
    float r; asm("ex2.approx.f32 %0, %1;" : "=f"(r) : "f"(x)); return r;
}

// ---------------- scratch (allocation-free: device globals) ----------------
#define MD (8192 * 512)
#define WD (512 * 512)
__device__ __half g_qh[MD], g_kh[MD], g_vh[MD];
__device__ __half g_wqh[WD], g_wkh[WD], g_wvh[WD], g_woh[WD];
__device__ __half g_Qh[MD], g_Ql[MD], g_Kh[MD], g_Vh[MD];
__device__ __half g_ch[MD];

// ---------------------------------------------------------------------------
// Convert: 7 tensors, single fp16 plane each. float4 granular.
// ---------------------------------------------------------------------------
struct CvtArgs {
    const float* src[7];
    __half* dst[7];
};
#define MD4 (MD / 4)
#define WD4 (WD / 4)
__global__ void convert_all(CvtArgs a)
{
    const int total = 3 * MD4 + 4 * WD4;
    for (int i = blockIdx.x * blockDim.x + threadIdx.x; i < total;
         i += gridDim.x * blockDim.x) {
        int s, off;
        if (i < 3 * MD4) { s = i >> 20; off = i & (MD4 - 1); }
        else { int j = i - 3 * MD4; s = 3 + (j >> 16); off = j & (WD4 - 1); }
        float4 v = ((const float4*)a.src[s])[off];
        uint2 h;
        h.x = pkh(v.x, v.y); h.y = pkh(v.z, v.w);
        ((uint2*)a.dst[s])[off] = h;
    }
}

// ---------------------------------------------------------------------------
// GEMM: C[8192,512] = A @ W^T (+bias)(*scale). A,W single fp16 planes.
// Tile 128Mx128N, BK=64 (8 steps), 256 threads, warps 4(M)x2(N) = 32x64 each.
// 2-stage cp.async, 2 CTA/SM (smem 73728B). grid (4 n, 64 m, z).
// smem/stage: Ah 128x144B @0, Wh 128x144B @18432 -> 36864B.
// ---------------------------------------------------------------------------
#define GSTG 36864
#define GSMEM (2 * GSTG)
struct G3Args {
    const __half* Ah[3];
    const __half* Wh[3];
    const float* bias[3];
    float scale[3];
    float* Cf[3];
    __half* Ch[3];
    __half* Cl[3];   // null => single-plane fp16 output
};
template <int OUT_SPLIT>
__global__ void __launch_bounds__(256, 2)
gemm3(G3Args ga)
{
    extern __shared__ __align__(16) unsigned char dsm[];
    const unsigned smb = sptr(dsm);
    const int z = blockIdx.z;
    const __half* __restrict__ Ahi = ga.Ah[z];
    const __half* __restrict__ Whi = ga.Wh[z];
    const float* __restrict__ bias = ga.bias[z];
    const float scale = ga.scale[z];

    const int tid = threadIdx.x, w = tid >> 5, lane = tid & 31;
    const int wm = w >> 1, wn = w & 1;              // 4(M) x 2(N)
    const int m0 = blockIdx.y * 128, n0 = blockIdx.x * 128;

    float acc[2][8][4];
#pragma unroll
    for (int a = 0; a < 2; a++)
#pragma unroll
        for (int b = 0; b < 8; b++)
#pragma unroll
            for (int c = 0; c < 4; c++) acc[a][b][c] = 0.f;

#pragma unroll 1
    for (int step = -1; step < 8; step++) {
        int lt = step + 1;
        if (lt < 8) {
            unsigned sdst = smb + (lt & 1) * GSTG;
            int k0 = lt * 64;
#pragma unroll
            for (int c = 0; c < 8; c++) {
                int idx = tid + c * 256;           // 0..2047
                if (idx < 1024) {                  // A: 128 rows x 8 chunks
                    int r = idx >> 3, q = idx & 7;
                    cpasync16(sdst + r * 144 + q * 16,
                              Ahi + (m0 + r) * 512 + k0 + q * 8);
                } else {                           // W: 128 rows x 8 chunks
                    int j = idx - 1024;
                    int r = j >> 3, q = j & 7;
                    cpasync16(sdst + 18432 + r * 144 + q * 16,
                              Whi + (n0 + r) * 512 + k0 + q * 8);
                }
            }
            cpcommit();
        }
        if (step < 0) continue;
        if (step < 7) cpwait<1>(); else cpwait<0>();
        __syncthreads();

        unsigned sa = smb + (step & 1) * GSTG;
#pragma unroll
        for (int ks = 0; ks < 4; ks++) {
            unsigned bh[4][4];
#pragma unroll
            for (int np = 0; np < 4; np++) {
                unsigned boff = (wn * 64 + np * 16 + (lane & 7) + ((lane >> 4) << 3)) * 144
                                + ks * 32 + ((lane >> 3) & 1) * 16;
                ldsm4(bh[np], sa + 18432 + boff);
            }
            unsigned ah[2][4];
#pragma unroll
            for (int mi = 0; mi < 2; mi++) {
                unsigned aoff = (wm * 32 + mi * 16 + (lane & 15)) * 144
                                + ks * 32 + (lane >> 4) * 16;
                ldsm4(ah[mi], sa + aoff);
            }
#pragma unroll
            for (int mi = 0; mi < 2; mi++) {
#pragma unroll
                for (int np = 0; np < 4; np++) {
                    mma16816(acc[mi][np * 2],     ah[mi], bh[np]);
                    mma16816(acc[mi][np * 2 + 1], ah[mi], bh[np] + 2);
                }
            }
        }
        __syncthreads();
    }

    // epilogue
    const bool has_lo = OUT_SPLIT && (ga.Cl[z] != nullptr);
#pragma unroll
    for (int mi = 0; mi < 2; mi++) {
#pragma unroll
        for (int j = 0; j < 8; j++) {
            int n = n0 + wn * 64 + j * 8 + (lane & 3) * 2;
            float b0 = bias[n], b1 = bias[n + 1];
#pragma unroll
            for (int rr = 0; rr < 2; rr++) {
                int m = m0 + wm * 32 + mi * 16 + (lane >> 2) + rr * 8;
                float v0 = (acc[mi][j][rr * 2]     + b0) * scale;
                float v1 = (acc[mi][j][rr * 2 + 1] + b1) * scale;
                if (OUT_SPLIT) {
                    int bb = m >> 11, s = m & 2047, hh = n >> 6, hd = n & 63;
                    int o = (((bb << 3) + hh) * 2048 + s) * 64 + hd;
                    if (has_lo) {
                        unsigned hv, lv; split2h(v0, v1, hv, lv);
                        *(unsigned*)&ga.Ch[z][o] = hv;
                        *(unsigned*)&ga.Cl[z][o] = lv;
                    } else {
                        *(unsigned*)&ga.Ch[z][o] = pkh(v0, v1);
                    }
                } else {
                    *(float2*)&ga.Cf[z][m * 512 + n] = make_float2(v0, v1);
                }
            }
        }
    }
}

// ---------------------------------------------------------------------------
// Flash attention (unchanged from R10). Block = (b,h,64 q rows), 128 thr,
// 3 CTA/SM. S: Q hi+lo (2-term) x K. PV: P single (1-term) x V.
// ctx single fp16 plane. log2-domain softmax.
// smem/stage: Kh 64x144B @0, Vh @9216 -> 18432B; 2 stages.
// ---------------------------------------------------------------------------
#define ASTG 18432
#define ATTN_SMEM (2 * ASTG)
__global__ void __launch_bounds__(128, 3)
attn_kernel(const __half* __restrict__ Qh_, const __half* __restrict__ Ql_,
            const __half* __restrict__ Kh_, const __half* __restrict__ Vh_,
            __half* __restrict__ Ch)
{
    extern __shared__ __align__(16) unsigned char dsm[];
    const unsigned smb = sptr(dsm);
    const int tid = threadIdx.x, w = tid >> 5, lane = tid & 31;
    const int q0 = blockIdx.x * 64;
    const int h = blockIdx.y, b = blockIdx.z;
    const long base = (long)((b << 3) + h) * (2048 * 64);

    // ---- Q tile (64 rows, hi+lo) -> smem stage0 area -> registers ----
#pragma unroll
    for (int c = 0; c < 8; c++) {
        int idx = tid + c * 128;                 // 0..1023
        int p = idx >> 9, r = (idx >> 3) & 63, q = idx & 7;
        const __half* src = (p ? Ql_ : Qh_) + base + (long)(q0 + r) * 64 + q * 8;
        cpasync16(smb + p * 9216 + r * 144 + q * 16, src);
    }
    cpcommit(); cpwait<0>();
    __syncthreads();

    unsigned qh[4][4], ql[4][4];
#pragma unroll
    for (int ks = 0; ks < 4; ks++) {
        unsigned off = (w * 16 + (lane & 15)) * 144 + ks * 32 + (lane >> 4) * 16;
        ldsm4(qh[ks], smb + off);
        ldsm4(ql[ks], smb + 9216 + off);
    }
    __syncthreads();

    float o[8][4];
#pragma unroll
    for (int j = 0; j < 8; j++)
#pragma unroll
        for (int i = 0; i < 4; i++) o[j][i] = 0.f;
    float rm[2] = {-1e30f, -1e30f}, rl[2] = {0.f, 0.f};

#pragma unroll 1
    for (int t = -1; t < 32; t++) {
        int lt = t + 1;
        if (lt < 32) {  // prefetch K/V tile lt (single planes)
            unsigned sdst = smb + (lt & 1) * ASTG;
            long coff = base + (long)lt * 64 * 64;
#pragma unroll
            for (int c = 0; c < 8; c++) {
                int idx = tid + c * 128;         // 0..1023
                int p = idx >> 9, r = (idx >> 3) & 63, q = idx & 7;
                const __half* sp = p ? Vh_ : Kh_;
                cpasync16(sdst + p * 9216 + r * 144 + q * 16, sp + coff + r * 64 + q * 8);
            }
            cpcommit();
        }
        if (t < 0) continue;
        if (t < 31) cpwait<1>(); else cpwait<0>();
        __syncthreads();

        unsigned stb = smb + (t & 1) * ASTG;

        // ---- S = Q @ K^T (log2-domain scores), 2-term: qh*kh + ql*kh ----
        float s[8][4];
#pragma unroll
        for (int j = 0; j < 8; j++)
#pragma unroll
            for (int i = 0; i < 4; i++) s[j][i] = 0.f;

#pragma unroll
        for (int ks = 0; ks < 4; ks++) {
            unsigned kh[4][4];
#pragma unroll
            for (int np = 0; np < 4; np++) {
                unsigned boff = (np * 16 + (lane & 7) + ((lane >> 4) << 3)) * 144
                                + ks * 32 + ((lane >> 3) & 1) * 16;
                ldsm4(kh[np], stb + boff);
            }
#pragma unroll
            for (int term = 0; term < 2; term++) {
                const unsigned* a = term ? ql[ks] : qh[ks];
#pragma unroll
                for (int np = 0; np < 4; np++) {
                    mma16816(s[np * 2],     a, kh[np]);
                    mma16816(s[np * 2 + 1], a, kh[np] + 2);
                }
            }
        }

        // ---- online softmax (base-2) ----
#pragma unroll
        for (int rr = 0; rr < 2; rr++) {
            float mt = -1e30f;
#pragma unroll
            for (int j = 0; j < 8; j++)
                mt = fmaxf(mt, fmaxf(s[j][rr * 2], s[j][rr * 2 + 1]));
            mt = fmaxf(mt, __shfl_xor_sync(0xffffffffu, mt, 1));
            mt = fmaxf(mt, __shfl_xor_sync(0xffffffffu, mt, 2));
            float mn = fmaxf(rm[rr], mt);
            float corr = ex2(rm[rr] - mn);
            rm[rr] = mn;
            float ls = 0.f;
#pragma unroll
            for (int j = 0; j < 8; j++) {
                float p0 = ex2(s[j][rr * 2] - mn);
                float p1 = ex2(s[j][rr * 2 + 1] - mn);
                s[j][rr * 2] = p0; s[j][rr * 2 + 1] = p1;
                ls += p0 + p1;
            }
            ls += __shfl_xor_sync(0xffffffffu, ls, 1);
            ls += __shfl_xor_sync(0xffffffffu, ls, 2);
            rl[rr] = rl[rr] * corr + ls;
#pragma unroll
            for (int j = 0; j < 8; j++) {
                o[j][rr * 2] *= corr; o[j][rr * 2 + 1] *= corr;
            }
        }

        // ---- P fragments, single fp16 (S C-frag layout == PV A-frag layout) ----
        unsigned ph[4][4];
#pragma unroll
        for (int kc = 0; kc < 4; kc++) {
            ph[kc][0] = pkh(s[2 * kc][0],     s[2 * kc][1]);
            ph[kc][1] = pkh(s[2 * kc][2],     s[2 * kc][3]);
            ph[kc][2] = pkh(s[2 * kc + 1][0], s[2 * kc + 1][1]);
            ph[kc][3] = pkh(s[2 * kc + 1][2], s[2 * kc + 1][3]);
        }

        // ---- O += P @ V, 1-term ----
#pragma unroll
        for (int ks = 0; ks < 4; ks++) {
            unsigned vrow = ks * 16 + (lane & 7) + ((lane >> 3) & 1) * 8;
#pragma unroll
            for (int dp = 0; dp < 4; dp++) {
                unsigned vh[4];
                unsigned off = vrow * 144 + dp * 32 + (lane >> 4) * 16;
                ldsm4t(vh, stb + 9216 + off);
                mma16816(o[dp * 2],     ph[ks], vh);
                mma16816(o[dp * 2 + 1], ph[ks], vh + 2);
            }
        }
        __syncthreads();
    }

    // ---- normalize, write ctx single fp16 plane [B,S,D] ----
#pragma unroll
    for (int rr = 0; rr < 2; rr++) {
        float inv = 1.f / rl[rr];
        int rg = q0 + w * 16 + (lane >> 2) + rr * 8;
#pragma unroll
        for (int j = 0; j < 8; j++) {
            int col = h * 64 + j * 8 + (lane & 3) * 2;
            int oix = (b * 2048 + rg) * 512 + col;
            *(unsigned*)&Ch[oix] = pkh(o[j][rr * 2] * inv, o[j][rr * 2 + 1] * inv);
        }
    }
}

// ---------------------------------------------------------------------------
extern "C" void kernel_launch(void* const* d_in, const int* in_sizes, int n_in,
                              void* d_out, int out_size)
{
    const float* q  = (const float*)d_in[0];
    const float* k  = (const float*)d_in[1];
    const float* v  = (const float*)d_in[2];
    const float* Wq = (const float*)d_in[3];
    const float* bq = (const float*)d_in[4];
    const float* Wk = (const float*)d_in[5];
    const float* bk = (const float*)d_in[6];
    const float* Wv = (const float*)d_in[7];
    const float* bv = (const float*)d_in[8];
    const float* Wo = (const float*)d_in[9];
    const float* bo = (const float*)d_in[10];

    __half *qh, *kh, *vh;
    __half *wqh, *wkh, *wvh, *woh;
    __half *Qh, *Ql, *Kh, *Vh, *ch;
    cudaGetSymbolAddress((void**)&qh, g_qh);
    cudaGetSymbolAddress((void**)&kh, g_kh);
    cudaGetSymbolAddress((void**)&vh, g_vh);
    cudaGetSymbolAddress((void**)&wqh, g_wqh); cudaGetSymbolAddress((void**)&wkh, g_wkh);
    cudaGetSymbolAddress((void**)&wvh, g_wvh); cudaGetSymbolAddress((void**)&woh, g_woh);
    cudaGetSymbolAddress((void**)&Qh, g_Qh);   cudaGetSymbolAddress((void**)&Ql, g_Ql);
    cudaGetSymbolAddress((void**)&Kh, g_Kh);   cudaGetSymbolAddress((void**)&Vh, g_Vh);
    cudaGetSymbolAddress((void**)&ch, g_ch);

    cudaFuncSetAttribute((const void*)gemm3<0>,
                         cudaFuncAttributeMaxDynamicSharedMemorySize, GSMEM);
    cudaFuncSetAttribute((const void*)gemm3<1>,
                         cudaFuncAttributeMaxDynamicSharedMemorySize, GSMEM);
    cudaFuncSetAttribute(attn_kernel, cudaFuncAttributeMaxDynamicSharedMemorySize, ATTN_SMEM);

    // 0) one convert kernel, single plane per tensor
    CvtArgs ca = {};
    ca.src[0] = q;  ca.dst[0] = qh;
    ca.src[1] = k;  ca.dst[1] = kh;
    ca.src[2] = v;  ca.dst[2] = vh;
    ca.src[3] = Wq; ca.dst[3] = wqh;
    ca.src[4] = Wk; ca.dst[4] = wkh;
    ca.src[5] = Wv; ca.dst[5] = wvh;
    ca.src[6] = Wo; ca.dst[6] = woh;
    convert_all<<<2048, 256>>>(ca);

    // 1) merged QKV projections (Q pre-scaled by 0.125*log2e; Q output split)
    const float qscale = 0.125f * 1.44269504088896f;
    G3Args gq = {};
    gq.Ah[0] = qh; gq.Wh[0] = wqh; gq.bias[0] = bq; gq.scale[0] = qscale;
    gq.Ch[0] = Qh; gq.Cl[0] = Ql;
    gq.Ah[1] = kh; gq.Wh[1] = wkh; gq.bias[1] = bk; gq.scale[1] = 1.0f;
    gq.Ch[1] = Kh; gq.Cl[1] = nullptr;
    gq.Ah[2] = vh; gq.Wh[2] = wvh; gq.bias[2] = bv; gq.scale[2] = 1.0f;
    gq.Ch[2] = Vh; gq.Cl[2] = nullptr;
    gemm3<1><<<dim3(4, 64, 3), 256, GSMEM>>>(gq);

    // 2) attention: 1024 CTAs x 128 threads, 64 q-rows each
    attn_kernel<<<dim3(32, 8, 4), 128, ATTN_SMEM>>>(Qh, Ql, Kh, Vh, ch);

    // 3) output projection (fp32 out + bias), 256 CTAs = single wave
    G3Args go = {};
    go.Ah[0] = ch; go.Wh[0] = woh; go.bias[0] = bo; go.scale[0] = 1.0f;
    go.Cf[0] = (float*)d_out;
    gemm3<0><<<dim3(4, 64, 1), 256, GSMEM>>>(go);
}

// round 12
// speedup vs baseline: 2.2576x; 1.1155x over previous
#include <cuda_runtime.h>
#include <cuda_fp16.h>

// ---------------------------------------------------------------------------
// MHA, fp16 mma.sync, all matmuls 1-term (pure fp16 operands, fp32 accum).
// B=4, S=2048, D=512, H=8, HD=64.
//  0) convert: q,k,v,W* -> single fp16 plane each
//  1) merged QKV proj GEMM, 128x128 tiles, 256 thr, 2 CTA/SM, [B,H,S,HD] remap
//  2) flash attn: 128 thr, 64 q-rows, 3 CTA/SM, log2-domain softmax
//  3) out GEMM (ctx x Wo -> fp32 + bias), 256 CTAs = single wave
// Error stack (RMS, model validated 6 rounds): 4xW + q,k,v + Q,P,ctx
//   intermediates => ~7.3e-4 < 1e-3.
// HMMA issue ceiling ~683 MAC/cyc/SM binds attn; GEMMs near it + L2.
// ---------------------------------------------------------------------------

#define DI __device__ __forceinline__

DI unsigned sptr(const void* p) { return (unsigned)__cvta_generic_to_shared(p); }

DI void cpasync16(unsigned dst, const void* src) {
    asm volatile("cp.async.cg.shared.global [%0], [%1], 16;" :: "r"(dst), "l"(src));
}
DI void cpcommit() { asm volatile("cp.async.commit_group;"); }
template <int N> DI void cpwait() { asm volatile("cp.async.wait_group %0;" :: "n"(N)); }

DI void ldsm4(unsigned* r, unsigned a) {
    asm volatile("ldmatrix.sync.aligned.m8n8.x4.shared.b16 {%0,%1,%2,%3}, [%4];"
                 : "=r"(r[0]), "=r"(r[1]), "=r"(r[2]), "=r"(r[3]) : "r"(a));
}
DI void ldsm4t(unsigned* r, unsigned a) {
    asm volatile("ldmatrix.sync.aligned.m8n8.x4.trans.shared.b16 {%0,%1,%2,%3}, [%4];"
                 : "=r"(r[0]), "=r"(r[1]), "=r"(r[2]), "=r"(r[3]) : "r"(a));
}
DI void mma16816(float* c, const unsigned* a, const unsigned* b) {
    asm volatile(
        "mma.sync.aligned.m16n8k16.row.col.f32.f16.f16.f32 "
        "{%0,%1,%2,%3},{%4,%5,%6,%7},{%8,%9},{%0,%1,%2,%3};"
        : "+f"(c[0]), "+f"(c[1]), "+f"(c[2]), "+f"(c[3])
        : "r"(a[0]), "r"(a[1]), "r"(a[2]), "r"(a[3]), "r"(b[0]), "r"(b[1]));
}
DI unsigned pkh(float e0, float e1) {   // pack (e0,e1) -> half2, e0 low
    __half2 h = __floats2half2_rn(e0, e1);
    return *(unsigned*)&h;
}
DI float ex2(float x) {
    float r; asm("ex2.approx.f32 %0, %1;" : "=f"(r) : "f"(x)); return r;
}

// ---------------- scratch (allocation-free: device globals) ----------------
#define MD (8192 * 512)
#define WD (512 * 512)
__device__ __half g_qh[MD], g_kh[MD], g_vh[MD];
__device__ __half g_wqh[WD], g_wkh[WD], g_wvh[WD], g_woh[WD];
__device__ __half g_Qh[MD], g_Kh[MD], g_Vh[MD];
__device__ __half g_ch[MD];

// ---------------------------------------------------------------------------
// Convert: 7 tensors, single fp16 plane each. float4 granular.
// ---------------------------------------------------------------------------
struct CvtArgs {
    const float* src[7];
    __half* dst[7];
};
#define MD4 (MD / 4)
#define WD4 (WD / 4)
__global__ void convert_all(CvtArgs a)
{
    const int total = 3 * MD4 + 4 * WD4;
    for (int i = blockIdx.x * blockDim.x + threadIdx.x; i < total;
         i += gridDim.x * blockDim.x) {
        int s, off;
        if (i < 3 * MD4) { s = i >> 20; off = i & (MD4 - 1); }
        else { int j = i - 3 * MD4; s = 3 + (j >> 16); off = j & (WD4 - 1); }
        float4 v = ((const float4*)a.src[s])[off];
        uint2 h;
        h.x = pkh(v.x, v.y); h.y = pkh(v.z, v.w);
        ((uint2*)a.dst[s])[off] = h;
    }
}

// ---------------------------------------------------------------------------
// GEMM: C[8192,512] = A @ W^T (+bias)(*scale). A,W single fp16 planes.
// Tile 128Mx128N, BK=64 (8 steps), 256 threads, warps 4(M)x2(N) = 32x64 each.
// 2-stage cp.async, 2 CTA/SM. grid (4 n, 64 m, z).
// REMAP=1: fp16 out in [B,H,S,HD]; REMAP=0: fp32 out row-major + bias.
// smem/stage: Ah 128x144B @0, Wh 128x144B @18432 -> 36864B.
// ---------------------------------------------------------------------------
#define GSTG 36864
#define GSMEM (2 * GSTG)
struct G3Args {
    const __half* Ah[3];
    const __half* Wh[3];
    const float* bias[3];
    float scale[3];
    float* Cf[3];
    __half* Ch[3];
};
template <int REMAP>
__global__ void __launch_bounds__(256, 2)
gemm3(G3Args ga)
{
    extern __shared__ __align__(16) unsigned char dsm[];
    const unsigned smb = sptr(dsm);
    const int z = blockIdx.z;
    const __half* __restrict__ Ahi = ga.Ah[z];
    const __half* __restrict__ Whi = ga.Wh[z];
    const float* __restrict__ bias = ga.bias[z];
    const float scale = ga.scale[z];

    const int tid = threadIdx.x, w = tid >> 5, lane = tid & 31;
    const int wm = w >> 1, wn = w & 1;              // 4(M) x 2(N)
    const int m0 = blockIdx.y * 128, n0 = blockIdx.x * 128;

    float acc[2][8][4];
#pragma unroll
    for (int a = 0; a < 2; a++)
#pragma unroll
        for (int b = 0; b < 8; b++)
#pragma unroll
            for (int c = 0; c < 4; c++) acc[a][b][c] = 0.f;

#pragma unroll 1
    for (int step = -1; step < 8; step++) {
        int lt = step + 1;
        if (lt < 8) {
            unsigned sdst = smb + (lt & 1) * GSTG;
            int k0 = lt * 64;
#pragma unroll
            for (int c = 0; c < 8; c++) {
                int idx = tid + c * 256;           // 0..2047
                if (idx < 1024) {                  // A: 128 rows x 8 chunks
                    int r = idx >> 3, q = idx & 7;
                    cpasync16(sdst + r * 144 + q * 16,
                              Ahi + (m0 + r) * 512 + k0 + q * 8);
                } else {                           // W: 128 rows x 8 chunks
                    int j = idx - 1024;
                    int r = j >> 3, q = j & 7;
                    cpasync16(sdst + 18432 + r * 144 + q * 16,
                              Whi + (n0 + r) * 512 + k0 + q * 8);
                }
            }
            cpcommit();
        }
        if (step < 0) continue;
        if (step < 7) cpwait<1>(); else cpwait<0>();
        __syncthreads();

        unsigned sa = smb + (step & 1) * GSTG;
#pragma unroll
        for (int ks = 0; ks < 4; ks++) {
            unsigned bh[4][4];
#pragma unroll
            for (int np = 0; np < 4; np++) {
                unsigned boff = (wn * 64 + np * 16 + (lane & 7) + ((lane >> 4) << 3)) * 144
                                + ks * 32 + ((lane >> 3) & 1) * 16;
                ldsm4(bh[np], sa + 18432 + boff);
            }
            unsigned ah[2][4];
#pragma unroll
            for (int mi = 0; mi < 2; mi++) {
                unsigned aoff = (wm * 32 + mi * 16 + (lane & 15)) * 144
                                + ks * 32 + (lane >> 4) * 16;
                ldsm4(ah[mi], sa + aoff);
            }
#pragma unroll
            for (int mi = 0; mi < 2; mi++) {
#pragma unroll
                for (int np = 0; np < 4; np++) {
                    mma16816(acc[mi][np * 2],     ah[mi], bh[np]);
                    mma16816(acc[mi][np * 2 + 1], ah[mi], bh[np] + 2);
                }
            }
        }
        __syncthreads();
    }

    // epilogue
#pragma unroll
    for (int mi = 0; mi < 2; mi++) {
#pragma unroll
        for (int j = 0; j < 8; j++) {
            int n = n0 + wn * 64 + j * 8 + (lane & 3) * 2;
            float b0 = bias[n], b1 = bias[n + 1];
#pragma unroll
            for (int rr = 0; rr < 2; rr++) {
                int m = m0 + wm * 32 + mi * 16 + (lane >> 2) + rr * 8;
                float v0 = (acc[mi][j][rr * 2]     + b0) * scale;
                float v1 = (acc[mi][j][rr * 2 + 1] + b1) * scale;
                if (REMAP) {
                    int bb = m >> 11, s = m & 2047, hh = n >> 6, hd = n & 63;
                    int o = (((bb << 3) + hh) * 2048 + s) * 64 + hd;
                    *(unsigned*)&ga.Ch[z][o] = pkh(v0, v1);
                } else {
                    *(float2*)&ga.Cf[z][m * 512 + n] = make_float2(v0, v1);
                }
            }
        }
    }
}

// ---------------------------------------------------------------------------
// Flash attention. Block = (b,h,64 q rows), 128 threads, 3 CTA/SM.
// All matmuls 1-term fp16. log2-domain softmax (Q pre-scaled 0.125*log2e).
// smem/stage: Kh 64x144B @0, Vh @9216 -> 18432B; 2 stages. Q staged in stage0.
// ---------------------------------------------------------------------------
#define ASTG 18432
#define ATTN_SMEM (2 * ASTG)
__global__ void __launch_bounds__(128, 3)
attn_kernel(const __half* __restrict__ Qh_, const __half* __restrict__ Kh_,
            const __half* __restrict__ Vh_, __half* __restrict__ Ch)
{
    extern __shared__ __align__(16) unsigned char dsm[];
    const unsigned smb = sptr(dsm);
    const int tid = threadIdx.x, w = tid >> 5, lane = tid & 31;
    const int q0 = blockIdx.x * 64;
    const int h = blockIdx.y, b = blockIdx.z;
    const long base = (long)((b << 3) + h) * (2048 * 64);

    // ---- Q tile (64 rows) -> smem stage0 area -> registers ----
#pragma unroll
    for (int c = 0; c < 4; c++) {
        int idx = tid + c * 128;                 // 0..511
        int r = idx >> 3, q = idx & 7;
        cpasync16(smb + r * 144 + q * 16, Qh_ + base + (long)(q0 + r) * 64 + q * 8);
    }
    cpcommit(); cpwait<0>();
    __syncthreads();

    unsigned qh[4][4];
#pragma unroll
    for (int ks = 0; ks < 4; ks++) {
        unsigned off = (w * 16 + (lane & 15)) * 144 + ks * 32 + (lane >> 4) * 16;
        ldsm4(qh[ks], smb + off);
    }
    __syncthreads();

    float o[8][4];
#pragma unroll
    for (int j = 0; j < 8; j++)
#pragma unroll
        for (int i = 0; i < 4; i++) o[j][i] = 0.f;
    float rm[2] = {-1e30f, -1e30f}, rl[2] = {0.f, 0.f};

#pragma unroll 1
    for (int t = -1; t < 32; t++) {
        int lt = t + 1;
        if (lt < 32) {  // prefetch K/V tile lt
            unsigned sdst = smb + (lt & 1) * ASTG;
            long coff = base + (long)lt * 64 * 64;
#pragma unroll
            for (int c = 0; c < 8; c++) {
                int idx = tid + c * 128;         // 0..1023
                int p = idx >> 9, r = (idx >> 3) & 63, q = idx & 7;
                const __half* sp = p ? Vh_ : Kh_;
                cpasync16(sdst + p * 9216 + r * 144 + q * 16, sp + coff + r * 64 + q * 8);
            }
            cpcommit();
        }
        if (t < 0) continue;
        if (t < 31) cpwait<1>(); else cpwait<0>();
        __syncthreads();

        unsigned stb = smb + (t & 1) * ASTG;

        // ---- S = Q @ K^T (log2-domain scores), 1-term ----
        float s[8][4];
#pragma unroll
        for (int j = 0; j < 8; j++)
#pragma unroll
            for (int i = 0; i < 4; i++) s[j][i] = 0.f;

#pragma unroll
        for (int ks = 0; ks < 4; ks++) {
#pragma unroll
            for (int np = 0; np < 4; np++) {
                unsigned kh[4];
                unsigned boff = (np * 16 + (lane & 7) + ((lane >> 4) << 3)) * 144
                                + ks * 32 + ((lane >> 3) & 1) * 16;
                ldsm4(kh, stb + boff);
                mma16816(s[np * 2],     qh[ks], kh);
                mma16816(s[np * 2 + 1], qh[ks], kh + 2);
            }
        }

        // ---- online softmax (base-2) ----
#pragma unroll
        for (int rr = 0; rr < 2; rr++) {
            float mt = -1e30f;
#pragma unroll
            for (int j = 0; j < 8; j++)
                mt = fmaxf(mt, fmaxf(s[j][rr * 2], s[j][rr * 2 + 1]));
            mt = fmaxf(mt, __shfl_xor_sync(0xffffffffu, mt, 1));
            mt = fmaxf(mt, __shfl_xor_sync(0xffffffffu, mt, 2));
            float mn = fmaxf(rm[rr], mt);
            float corr = ex2(rm[rr] - mn);
            rm[rr] = mn;
            float ls = 0.f;
#pragma unroll
            for (int j = 0; j < 8; j++) {
                float p0 = ex2(s[j][rr * 2] - mn);
                float p1 = ex2(s[j][rr * 2 + 1] - mn);
                s[j][rr * 2] = p0; s[j][rr * 2 + 1] = p1;
                ls += p0 + p1;
            }
            ls += __shfl_xor_sync(0xffffffffu, ls, 1);
            ls += __shfl_xor_sync(0xffffffffu, ls, 2);
            rl[rr] = rl[rr] * corr + ls;
#pragma unroll
            for (int j = 0; j < 8; j++) {
                o[j][rr * 2] *= corr; o[j][rr * 2 + 1] *= corr;
            }
        }

        // ---- P fragments, fp16 (S C-frag layout == PV A-frag layout) ----
        unsigned ph[4][4];
#pragma unroll
        for (int kc = 0; kc < 4; kc++) {
            ph[kc][0] = pkh(s[2 * kc][0],     s[2 * kc][1]);
            ph[kc][1] = pkh(s[2 * kc][2],     s[2 * kc][3]);
            ph[kc][2] = pkh(s[2 * kc + 1][0], s[2 * kc + 1][1]);
            ph[kc][3] = pkh(s[2 * kc + 1][2], s[2 * kc + 1][3]);
        }

        // ---- O += P @ V, 1-term ----
#pragma unroll
        for (int ks = 0; ks < 4; ks++) {
            unsigned vrow = ks * 16 + (lane & 7) + ((lane >> 3) & 1) * 8;
#pragma unroll
            for (int dp = 0; dp < 4; dp++) {
                unsigned vh[4];
                unsigned off = vrow * 144 + dp * 32 + (lane >> 4) * 16;
                ldsm4t(vh, stb + 9216 + off);
                mma16816(o[dp * 2],     ph[ks], vh);
                mma16816(o[dp * 2 + 1], ph[ks], vh + 2);
            }
        }
        __syncthreads();
    }

    // ---- normalize, write ctx fp16 plane [B,S,D] ----
#pragma unroll
    for (int rr = 0; rr < 2; rr++) {
        float inv = 1.f / rl[rr];
        int rg = q0 + w * 16 + (lane >> 2) + rr * 8;
#pragma unroll
        for (int j = 0; j < 8; j++) {
            int col = h * 64 + j * 8 + (lane & 3) * 2;
            int oix = (b * 2048 + rg) * 512 + col;
            *(unsigned*)&Ch[oix] = pkh(o[j][rr * 2] * inv, o[j][rr * 2 + 1] * inv);
        }
    }
}

// ---------------------------------------------------------------------------
extern "C" void kernel_launch(void* const* d_in, const int* in_sizes, int n_in,
                              void* d_out, int out_size)
{
    const float* q  = (const float*)d_in[0];
    const float* k  = (const float*)d_in[1];
    const float* v  = (const float*)d_in[2];
    const float* Wq = (const float*)d_in[3];
    const float* bq = (const float*)d_in[4];
    const float* Wk = (const float*)d_in[5];
    const float* bk = (const float*)d_in[6];
    const float* Wv = (const float*)d_in[7];
    const float* bv = (const float*)d_in[8];
    const float* Wo = (const float*)d_in[9];
    const float* bo = (const float*)d_in[10];

    __half *qh, *kh, *vh;
    __half *wqh, *wkh, *wvh, *woh;
    __half *Qh, *Kh, *Vh, *ch;
    cudaGetSymbolAddress((void**)&qh, g_qh);
    cudaGetSymbolAddress((void**)&kh, g_kh);
    cudaGetSymbolAddress((void**)&vh, g_vh);
    cudaGetSymbolAddress((void**)&wqh, g_wqh); cudaGetSymbolAddress((void**)&wkh, g_wkh);
    cudaGetSymbolAddress((void**)&wvh, g_wvh); cudaGetSymbolAddress((void**)&woh, g_woh);
    cudaGetSymbolAddress((void**)&Qh, g_Qh);
    cudaGetSymbolAddress((void**)&Kh, g_Kh);   cudaGetSymbolAddress((void**)&Vh, g_Vh);
    cudaGetSymbolAddress((void**)&ch, g_ch);

    cudaFuncSetAttribute((const void*)gemm3<0>,
                         cudaFuncAttributeMaxDynamicSharedMemorySize, GSMEM);
    cudaFuncSetAttribute((const void*)gemm3<1>,
                         cudaFuncAttributeMaxDynamicSharedMemorySize, GSMEM);
    cudaFuncSetAttribute(attn_kernel, cudaFuncAttributeMaxDynamicSharedMemorySize, ATTN_SMEM);

    // 0) one convert kernel, single plane per tensor
    CvtArgs ca = {};
    ca.src[0] = q;  ca.dst[0] = qh;
    ca.src[1] = k;  ca.dst[1] = kh;
    ca.src[2] = v;  ca.dst[2] = vh;
    ca.src[3] = Wq; ca.dst[3] = wqh;
    ca.src[4] = Wk; ca.dst[4] = wkh;
    ca.src[5] = Wv; ca.dst[5] = wvh;
    ca.src[6] = Wo; ca.dst[6] = woh;
    convert_all<<<2048, 256>>>(ca);

    // 1) merged QKV projections (Q pre-scaled by 0.125*log2e for base-2 softmax)
    const float qscale = 0.125f * 1.44269504088896f;
    G3Args gq = {};
    gq.Ah[0] = qh; gq.Wh[0] = wqh; gq.bias[0] = bq; gq.scale[0] = qscale; gq.Ch[0] = Qh;
    gq.Ah[1] = kh; gq.Wh[1] = wkh; gq.bias[1] = bk; gq.scale[1] = 1.0f;   gq.Ch[1] = Kh;
    gq.Ah[2] = vh; gq.Wh[2] = wvh; gq.bias[2] = bv; gq.scale[2] = 1.0f;   gq.Ch[2] = Vh;
    gemm3<1><<<dim3(4, 64, 3), 256, GSMEM>>>(gq);

    // 2) attention: 1024 CTAs x 128 threads, 64 q-rows each
    attn_kernel<<<dim3(32, 8, 4), 128, ATTN_SMEM>>>(Qh, Kh, Vh, ch);

    // 3) output projection (fp32 out + bias), 256 CTAs = single wave
    G3Args go = {};
    go.Ah[0] = ch; go.Wh[0] = woh; go.bias[0] = bo; go.scale[0] = 1.0f;
    go.Cf[0] = (float*)d_out;
    gemm3<0><<<dim3(4, 64, 1), 256, GSMEM>>>(go);
}

// round 13
// speedup vs baseline: 2.2959x; 1.0169x over previous
#include <cuda_runtime.h>
#include <cuda_fp16.h>

// ---------------------------------------------------------------------------
// MHA, fp16 mma.sync, all matmuls 1-term. 3-stage cp.async pipelines.
// B=4, S=2048, D=512, H=8, HD=64.
//  0) convert: q,k,v,W* -> single fp16 plane each
//  1) merged QKV proj GEMM, 128x128 tiles, 256 thr, 2 CTA/SM, 3-stage
//  2) flash attn: 128 thr, 64 q-rows, 3 CTA/SM, 3-stage K/V, log2 softmax
//  3) out GEMM (ctx x Wo -> fp32 + bias), single wave, 3-stage
// Error stack unchanged from R12 (measured 7.26e-4 < 1e-3).
// ---------------------------------------------------------------------------

#define DI __device__ __forceinline__

DI unsigned sptr(const void* p) { return (unsigned)__cvta_generic_to_shared(p); }

DI void cpasync16(unsigned dst, const void* src) {
    asm volatile("cp.async.cg.shared.global [%0], [%1], 16;" :: "r"(dst), "l"(src));
}
DI void cpcommit() { asm volatile("cp.async.commit_group;"); }
template <int N> DI void cpwait() { asm volatile("cp.async.wait_group %0;" :: "n"(N)); }

DI void ldsm4(unsigned* r, unsigned a) {
    asm volatile("ldmatrix.sync.aligned.m8n8.x4.shared.b16 {%0,%1,%2,%3}, [%4];"
                 : "=r"(r[0]), "=r"(r[1]), "=r"(r[2]), "=r"(r[3]) : "r"(a));
}
DI void ldsm4t(unsigned* r, unsigned a) {
    asm volatile("ldmatrix.sync.aligned.m8n8.x4.trans.shared.b16 {%0,%1,%2,%3}, [%4];"
                 : "=r"(r[0]), "=r"(r[1]), "=r"(r[2]), "=r"(r[3]) : "r"(a));
}
DI void mma16816(float* c, const unsigned* a, const unsigned* b) {
    asm volatile(
        "mma.sync.aligned.m16n8k16.row.col.f32.f16.f16.f32 "
        "{%0,%1,%2,%3},{%4,%5,%6,%7},{%8,%9},{%0,%1,%2,%3};"
        : "+f"(c[0]), "+f"(c[1]), "+f"(c[2]), "+f"(c[3])
        : "r"(a[0]), "r"(a[1]), "r"(a[2]), "r"(a[3]), "r"(b[0]), "r"(b[1]));
}
DI unsigned pkh(float e0, float e1) {   // pack (e0,e1) -> half2, e0 low
    __half2 h = __floats2half2_rn(e0, e1);
    return *(unsigned*)&h;
}
DI float ex2(float x) {
    float r; asm("ex2.approx.f32 %0, %1;" : "=f"(r) : "f"(x)); return r;
}

// ---------------- scratch (allocation-free: device globals) ----------------
#define MD (8192 * 512)
#define WD (512 * 512)
__device__ __half g_qh[MD], g_kh[MD], g_vh[MD];
__device__ __half g_wqh[WD], g_wkh[WD], g_wvh[WD], g_woh[WD];
__device__ __half g_Qh[MD], g_Kh[MD], g_Vh[MD];
__device__ __half g_ch[MD];

// ---------------------------------------------------------------------------
// Convert: 7 tensors, single fp16 plane each. float4 granular.
// ---------------------------------------------------------------------------
struct CvtArgs {
    const float* src[7];
    __half* dst[7];
};
#define MD4 (MD / 4)
#define WD4 (WD / 4)
__global__ void convert_all(CvtArgs a)
{
    const int total = 3 * MD4 + 4 * WD4;
    for (int i = blockIdx.x * blockDim.x + threadIdx.x; i < total;
         i += gridDim.x * blockDim.x) {
        int s, off;
        if (i < 3 * MD4) { s = i >> 20; off = i & (MD4 - 1); }
        else { int j = i - 3 * MD4; s = 3 + (j >> 16); off = j & (WD4 - 1); }
        float4 v = ((const float4*)a.src[s])[off];
        uint2 h;
        h.x = pkh(v.x, v.y); h.y = pkh(v.z, v.w);
        ((uint2*)a.dst[s])[off] = h;
    }
}

// ---------------------------------------------------------------------------
// GEMM: C[8192,512] = A @ W^T (+bias)(*scale). A,W single fp16 planes.
// Tile 128Mx128N, BK=64 (8 steps), 256 threads, warps 4(M)x2(N) = 32x64 each.
// 3-stage cp.async (prefetch distance 2), 2 CTA/SM. grid (4 n, 64 m, z).
// smem/stage: Ah 128x144B @0, Wh 128x144B @18432 -> 36864B; 3 stages.
// ---------------------------------------------------------------------------
#define GSTG 36864
#define GSMEM (3 * GSTG)
struct G3Args {
    const __half* Ah[3];
    const __half* Wh[3];
    const float* bias[3];
    float scale[3];
    float* Cf[3];
    __half* Ch[3];
};

template <int REMAP>
__global__ void __launch_bounds__(256, 2)
gemm3(G3Args ga)
{
    extern __shared__ __align__(16) unsigned char dsm[];
    const unsigned smb = sptr(dsm);
    const int z = blockIdx.z;
    const __half* __restrict__ Ahi = ga.Ah[z];
    const __half* __restrict__ Whi = ga.Wh[z];
    const float* __restrict__ bias = ga.bias[z];
    const float scale = ga.scale[z];

    const int tid = threadIdx.x, w = tid >> 5, lane = tid & 31;
    const int wm = w >> 1, wn = w & 1;              // 4(M) x 2(N)
    const int m0 = blockIdx.y * 128, n0 = blockIdx.x * 128;

    float acc[2][8][4];
#pragma unroll
    for (int a = 0; a < 2; a++)
#pragma unroll
        for (int b = 0; b < 8; b++)
#pragma unroll
            for (int c = 0; c < 4; c++) acc[a][b][c] = 0.f;

    // loader lambda-ish: issue K-chunk `ck` into stage `sg`
    const int arow = tid >> 3, aq = tid & 7;        // reused indices
#define G_ISSUE(ck, sg) do {                                                  \
        unsigned sdst = smb + (sg) * GSTG;                                    \
        int k0 = (ck) * 64;                                                   \
        _Pragma("unroll")                                                     \
        for (int c = 0; c < 8; c++) {                                         \
            int idx = tid + c * 256;                                          \
            if (idx < 1024) {                                                 \
                int r = idx >> 3, q = idx & 7;                                \
                cpasync16(sdst + r * 144 + q * 16,                            \
                          Ahi + (m0 + r) * 512 + k0 + q * 8);                 \
            } else {                                                          \
                int j = idx - 1024;                                           \
                int r = j >> 3, q = j & 7;                                    \
                cpasync16(sdst + 18432 + r * 144 + q * 16,                    \
                          Whi + (n0 + r) * 512 + k0 + q * 8);                 \
            }                                                                 \
        }                                                                     \
        cpcommit();                                                           \
    } while (0)

    // prologue: chunks 0,1 into stages 0,1
    G_ISSUE(0, 0);
    G_ISSUE(1, 1);

    int st = 0, stp = 2;   // current compute stage; prefetch target stage
#pragma unroll 1
    for (int step = 0; step < 8; step++) {
        if (step < 7) cpwait<1>(); else cpwait<0>();
        __syncthreads();
        if (step + 2 < 8) {
            G_ISSUE(step + 2, stp);
            if (++stp == 3) stp = 0;
        }

        unsigned sa = smb + st * GSTG;
        if (++st == 3) st = 0;
#pragma unroll
        for (int ks = 0; ks < 4; ks++) {
            unsigned bh[4][4];
#pragma unroll
            for (int np = 0; np < 4; np++) {
                unsigned boff = (wn * 64 + np * 16 + (lane & 7) + ((lane >> 4) << 3)) * 144
                                + ks * 32 + ((lane >> 3) & 1) * 16;
                ldsm4(bh[np], sa + 18432 + boff);
            }
            unsigned ah[2][4];
#pragma unroll
            for (int mi = 0; mi < 2; mi++) {
                unsigned aoff = (wm * 32 + mi * 16 + (lane & 15)) * 144
                                + ks * 32 + (lane >> 4) * 16;
                ldsm4(ah[mi], sa + aoff);
            }
#pragma unroll
            for (int mi = 0; mi < 2; mi++) {
#pragma unroll
                for (int np = 0; np < 4; np++) {
                    mma16816(acc[mi][np * 2],     ah[mi], bh[np]);
                    mma16816(acc[mi][np * 2 + 1], ah[mi], bh[np] + 2);
                }
            }
        }
    }
    (void)arow; (void)aq;

    // epilogue
#pragma unroll
    for (int mi = 0; mi < 2; mi++) {
#pragma unroll
        for (int j = 0; j < 8; j++) {
            int n = n0 + wn * 64 + j * 8 + (lane & 3) * 2;
            float b0 = bias[n], b1 = bias[n + 1];
#pragma unroll
            for (int rr = 0; rr < 2; rr++) {
                int m = m0 + wm * 32 + mi * 16 + (lane >> 2) + rr * 8;
                float v0 = (acc[mi][j][rr * 2]     + b0) * scale;
                float v1 = (acc[mi][j][rr * 2 + 1] + b1) * scale;
                if (REMAP) {
                    int bb = m >> 11, s = m & 2047, hh = n >> 6, hd = n & 63;
                    int o = (((bb << 3) + hh) * 2048 + s) * 64 + hd;
                    *(unsigned*)&ga.Ch[z][o] = pkh(v0, v1);
                } else {
                    *(float2*)&ga.Cf[z][m * 512 + n] = make_float2(v0, v1);
                }
            }
        }
    }
#undef G_ISSUE
}

// ---------------------------------------------------------------------------
// Flash attention. Block = (b,h,64 q rows), 128 threads, 3 CTA/SM.
// 1-term fp16 matmuls, log2-domain softmax (Q pre-scaled 0.125*log2e).
// smem: Q region 9216B @0; 3 K/V stages (Kh 64x144 @0, Vh @9216 per stage,
// 18432B each) starting @9216. Total 64512B -> 3 CTA/SM.
// Prefetch distance 2 tiles.
// ---------------------------------------------------------------------------
#define ASTG 18432
#define AQSZ 9216
#define ATTN_SMEM (AQSZ + 3 * ASTG)
__global__ void __launch_bounds__(128, 3)
attn_kernel(const __half* __restrict__ Qh_, const __half* __restrict__ Kh_,
            const __half* __restrict__ Vh_, __half* __restrict__ Ch)
{
    extern __shared__ __align__(16) unsigned char dsm[];
    const unsigned smb = sptr(dsm);
    const int tid = threadIdx.x, w = tid >> 5, lane = tid & 31;
    const int q0 = blockIdx.x * 64;
    const int h = blockIdx.y, b = blockIdx.z;
    const long base = (long)((b << 3) + h) * (2048 * 64);

#define A_ISSUE(tt, sg) do {                                                  \
        unsigned sdst = smb + AQSZ + (sg) * ASTG;                             \
        long coff = base + (long)(tt) * 64 * 64;                              \
        _Pragma("unroll")                                                     \
        for (int c = 0; c < 8; c++) {                                         \
            int idx = tid + c * 128;                                          \
            int p = idx >> 9, r = (idx >> 3) & 63, q = idx & 7;               \
            const __half* sp = p ? Vh_ : Kh_;                                 \
            cpasync16(sdst + p * 9216 + r * 144 + q * 16,                     \
                      sp + coff + r * 64 + q * 8);                            \
        }                                                                     \
        cpcommit();                                                           \
    } while (0)

    // ---- prologue: Q (own group) + tiles 0,1 ----
#pragma unroll
    for (int c = 0; c < 4; c++) {
        int idx = tid + c * 128;                 // 0..511
        int r = idx >> 3, q = idx & 7;
        cpasync16(smb + r * 144 + q * 16, Qh_ + base + (long)(q0 + r) * 64 + q * 8);
    }
    cpcommit();
    A_ISSUE(0, 0);
    A_ISSUE(1, 1);

    cpwait<2>();            // Q group complete
    __syncthreads();

    unsigned qh[4][4];
#pragma unroll
    for (int ks = 0; ks < 4; ks++) {
        unsigned off = (w * 16 + (lane & 15)) * 144 + ks * 32 + (lane >> 4) * 16;
        ldsm4(qh[ks], smb + off);
    }

    float o[8][4];
#pragma unroll
    for (int j = 0; j < 8; j++)
#pragma unroll
        for (int i = 0; i < 4; i++) o[j][i] = 0.f;
    float rm[2] = {-1e30f, -1e30f}, rl[2] = {0.f, 0.f};

    int st = 0, stp = 2;
#pragma unroll 1
    for (int t = 0; t < 32; t++) {
        if (t < 31) cpwait<1>(); else cpwait<0>();
        __syncthreads();
        if (t + 2 < 32) {
            A_ISSUE(t + 2, stp);
            if (++stp == 3) stp = 0;
        }

        unsigned stb = smb + AQSZ + st * ASTG;
        if (++st == 3) st = 0;

        // ---- S = Q @ K^T (log2-domain scores), 1-term ----
        float s[8][4];
#pragma unroll
        for (int j = 0; j < 8; j++)
#pragma unroll
            for (int i = 0; i < 4; i++) s[j][i] = 0.f;

#pragma unroll
        for (int ks = 0; ks < 4; ks++) {
#pragma unroll
            for (int np = 0; np < 4; np++) {
                unsigned kh[4];
                unsigned boff = (np * 16 + (lane & 7) + ((lane >> 4) << 3)) * 144
                                + ks * 32 + ((lane >> 3) & 1) * 16;
                ldsm4(kh, stb + boff);
                mma16816(s[np * 2],     qh[ks], kh);
                mma16816(s[np * 2 + 1], qh[ks], kh + 2);
            }
        }

        // ---- online softmax (base-2) ----
#pragma unroll
        for (int rr = 0; rr < 2; rr++) {
            float mt = -1e30f;
#pragma unroll
            for (int j = 0; j < 8; j++)
                mt = fmaxf(mt, fmaxf(s[j][rr * 2], s[j][rr * 2 + 1]));
            mt = fmaxf(mt, __shfl_xor_sync(0xffffffffu, mt, 1));
            mt = fmaxf(mt, __shfl_xor_sync(0xffffffffu, mt, 2));
            float mn = fmaxf(rm[rr], mt);
            float corr = ex2(rm[rr] - mn);
            rm[rr] = mn;
            float ls = 0.f;
#pragma unroll
            for (int j = 0; j < 8; j++) {
                float p0 = ex2(s[j][rr * 2] - mn);
                float p1 = ex2(s[j][rr * 2 + 1] - mn);
                s[j][rr * 2] = p0; s[j][rr * 2 + 1] = p1;
                ls += p0 + p1;
            }
            ls += __shfl_xor_sync(0xffffffffu, ls, 1);
            ls += __shfl_xor_sync(0xffffffffu, ls, 2);
            rl[rr] = rl[rr] * corr + ls;
#pragma unroll
            for (int j = 0; j < 8; j++) {
                o[j][rr * 2] *= corr; o[j][rr * 2 + 1] *= corr;
            }
        }

        // ---- P fragments, fp16 (S C-frag layout == PV A-frag layout) ----
        unsigned ph[4][4];
#pragma unroll
        for (int kc = 0; kc < 4; kc++) {
            ph[kc][0] = pkh(s[2 * kc][0],     s[2 * kc][1]);
            ph[kc][1] = pkh(s[2 * kc][2],     s[2 * kc][3]);
            ph[kc][2] = pkh(s[2 * kc + 1][0], s[2 * kc + 1][1]);
            ph[kc][3] = pkh(s[2 * kc + 1][2], s[2 * kc + 1][3]);
        }

        // ---- O += P @ V, 1-term ----
#pragma unroll
        for (int ks = 0; ks < 4; ks++) {
            unsigned vrow = ks * 16 + (lane & 7) + ((lane >> 3) & 1) * 8;
#pragma unroll
            for (int dp = 0; dp < 4; dp++) {
                unsigned vh[4];
                unsigned off = vrow * 144 + dp * 32 + (lane >> 4) * 16;
                ldsm4t(vh, stb + 9216 + off);
                mma16816(o[dp * 2],     ph[ks], vh);
                mma16816(o[dp * 2 + 1], ph[ks], vh + 2);
            }
        }
    }

    // ---- normalize, write ctx fp16 plane [B,S,D] ----
#pragma unroll
    for (int rr = 0; rr < 2; rr++) {
        float inv = 1.f / rl[rr];
        int rg = q0 + w * 16 + (lane >> 2) + rr * 8;
#pragma unroll
        for (int j = 0; j < 8; j++) {
            int col = h * 64 + j * 8 + (lane & 3) * 2;
            int oix = (b * 2048 + rg) * 512 + col;
            *(unsigned*)&Ch[oix] = pkh(o[j][rr * 2] * inv, o[j][rr * 2 + 1] * inv);
        }
    }
#undef A_ISSUE
}

// ---------------------------------------------------------------------------
extern "C" void kernel_launch(void* const* d_in, const int* in_sizes, int n_in,
                              void* d_out, int out_size)
{
    const float* q  = (const float*)d_in[0];
    const float* k  = (const float*)d_in[1];
    const float* v  = (const float*)d_in[2];
    const float* Wq = (const float*)d_in[3];
    const float* bq = (const float*)d_in[4];
    const float* Wk = (const float*)d_in[5];
    const float* bk = (const float*)d_in[6];
    const float* Wv = (const float*)d_in[7];
    const float* bv = (const float*)d_in[8];
    const float* Wo = (const float*)d_in[9];
    const float* bo = (const float*)d_in[10];

    __half *qh, *kh, *vh;
    __half *wqh, *wkh, *wvh, *woh;
    __half *Qh, *Kh, *Vh, *ch;
    cudaGetSymbolAddress((void**)&qh, g_qh);
    cudaGetSymbolAddress((void**)&kh, g_kh);
    cudaGetSymbolAddress((void**)&vh, g_vh);
    cudaGetSymbolAddress((void**)&wqh, g_wqh); cudaGetSymbolAddress((void**)&wkh, g_wkh);
    cudaGetSymbolAddress((void**)&wvh, g_wvh); cudaGetSymbolAddress((void**)&woh, g_woh);
    cudaGetSymbolAddress((void**)&Qh, g_Qh);
    cudaGetSymbolAddress((void**)&Kh, g_Kh);   cudaGetSymbolAddress((void**)&Vh, g_Vh);
    cudaGetSymbolAddress((void**)&ch, g_ch);

    cudaFuncSetAttribute((const void*)gemm3<0>,
                         cudaFuncAttributeMaxDynamicSharedMemorySize, GSMEM);
    cudaFuncSetAttribute((const void*)gemm3<1>,
                         cudaFuncAttributeMaxDynamicSharedMemorySize, GSMEM);
    cudaFuncSetAttribute(attn_kernel, cudaFuncAttributeMaxDynamicSharedMemorySize, ATTN_SMEM);

    // 0) one convert kernel, single plane per tensor
    CvtArgs ca = {};
    ca.src[0] = q;  ca.dst[0] = qh;
    ca.src[1] = k;  ca.dst[1] = kh;
    ca.src[2] = v;  ca.dst[2] = vh;
    ca.src[3] = Wq; ca.dst[3] = wqh;
    ca.src[4] = Wk; ca.dst[4] = wkh;
    ca.src[5] = Wv; ca.dst[5] = wvh;
    ca.src[6] = Wo; ca.dst[6] = woh;
    convert_all<<<2048, 256>>>(ca);

    // 1) merged QKV projections (Q pre-scaled by 0.125*log2e for base-2 softmax)
    const float qscale = 0.125f * 1.44269504088896f;
    G3Args gq = {};
    gq.Ah[0] = qh; gq.Wh[0] = wqh; gq.bias[0] = bq; gq.scale[0] = qscale; gq.Ch[0] = Qh;
    gq.Ah[1] = kh; gq.Wh[1] = wkh; gq.bias[1] = bk; gq.scale[1] = 1.0f;   gq.Ch[1] = Kh;
    gq.Ah[2] = vh; gq.Wh[2] = wvh; gq.bias[2] = bv; gq.scale[2] = 1.0f;   gq.Ch[2] = Vh;
    gemm3<1><<<dim3(4, 64, 3), 256, GSMEM>>>(gq);

    // 2) attention: 1024 CTAs x 128 threads, 64 q-rows each
    attn_kernel<<<dim3(32, 8, 4), 128, ATTN_SMEM>>>(Qh, Kh, Vh, ch);

    // 3) output projection (fp32 out + bias), 256 CTAs = single wave
    G3Args go = {};
    go.Ah[0] = ch; go.Wh[0] = woh; go.bias[0] = bo; go.scale[0] = 1.0f;
    go.Cf[0] = (float*)d_out;
    gemm3<0><<<dim3(4, 64, 1), 256, GSMEM>>>(go);
}